// round 4
// baseline (speedup 1.0000x reference)
#include <cuda_runtime.h>
#include <cuda_bf16.h>
#include <math.h>

// Problem constants (fixed by the dataset; runtime values checked against in_sizes)
#define MAXN 50048
#define MAXE 1600000

// ---------------- device scratch (static; no allocations allowed) ----------------
__device__ __align__(16) float g_dinv[MAXN];
__device__ __align__(16) int   g_deg[MAXN];
__device__ __align__(16) int   g_offs[MAXN + 1];
__device__ __align__(16) int   g_cursor[MAXN];
__device__ __align__(16) int   g_csr[MAXE];
__device__ __align__(16) float g_m[(size_t)MAXN * 128];
__device__ __align__(16) float g_agg[(size_t)MAXN * 128];
__device__ __align__(16) float g_proj[(size_t)MAXN * 128];
__device__ __align__(16) float g_h1[(size_t)MAXN * 64];
__device__ __align__(16) float g_out0[(size_t)MAXN * 128];
__device__ __align__(16) float g_out1[(size_t)MAXN * 128];
__device__ __align__(16) float g_hfc[(size_t)MAXN * 128];
__device__ __align__(16) float g_stats[256];
__device__ __align__(16) float g_ab[256];

// nan_to_num(nan=0, posinf=100, neginf=-100)
__device__ __forceinline__ float san(float v) {
    if (isnan(v)) return 0.f;
    if (isinf(v)) return v > 0.f ? 100.f : -100.f;
    return v;
}

// ---------------- degree / normalization ----------------
__global__ void deg_kernel(const int* __restrict__ col, int* __restrict__ deg, int E) {
    int e = blockIdx.x * blockDim.x + threadIdx.x;
    if (e < E) atomicAdd(&deg[col[e]], 1);
}

__global__ void dinv_kernel(const int* __restrict__ deg, float* __restrict__ dinv, int n) {
    int i = blockIdx.x * blockDim.x + threadIdx.x;
    if (i < n) {
        int d = deg[i];
        dinv[i] = d > 0 ? rsqrtf((float)d) : 0.f;
    }
}

// single-block exclusive scan of deg -> offs[0..n], cursor copy, offs[n]=E
__global__ void scan_kernel(const int* __restrict__ deg, int* __restrict__ offs,
                            int* __restrict__ cursor, int n) {
    __shared__ int wsum[32];
    __shared__ int carry_s;
    int tid = threadIdx.x;
    int lane = tid & 31, wid = tid >> 5;
    if (tid == 0) carry_s = 0;
    __syncthreads();
    int nIter = (n + 1023) >> 10;
    for (int it = 0; it < nIter; it++) {
        int i = (it << 10) + tid;
        int v = (i < n) ? deg[i] : 0;
        int x = v;
        #pragma unroll
        for (int off = 1; off < 32; off <<= 1) {
            int y = __shfl_up_sync(0xffffffffu, x, off);
            if (lane >= off) x += y;
        }
        if (lane == 31) wsum[wid] = x;
        __syncthreads();
        if (wid == 0) {
            int w = wsum[lane];
            #pragma unroll
            for (int off = 1; off < 32; off <<= 1) {
                int y = __shfl_up_sync(0xffffffffu, w, off);
                if (lane >= off) w += y;
            }
            wsum[lane] = w;
        }
        __syncthreads();
        int pre = (wid > 0) ? wsum[wid - 1] : 0;
        int total = wsum[31];
        int excl = carry_s + pre + x - v;
        if (i < n) { offs[i] = excl; cursor[i] = excl; }
        __syncthreads();
        if (tid == 0) carry_s += total;
        __syncthreads();
    }
    if (tid == 0) offs[n] = carry_s;
}

__global__ void csr_fill_kernel(const int* __restrict__ row, const int* __restrict__ col,
                                int* __restrict__ cursor, int* __restrict__ csr, int E) {
    int e = blockIdx.x * blockDim.x + threadIdx.x;
    if (e < E) {
        int pos = atomicAdd(&cursor[col[e]], 1);
        csr[pos] = row[e];
    }
}

// ---------------- register-tiled SGEMM: C[n,NOUT] = A[n,64] @ B[64,NOUT] ----------------
template <int NOUT>
__global__ __launch_bounds__(256) void sgemm64_kernel(const float* __restrict__ A,
                                                      const float* __restrict__ B,
                                                      float* __restrict__ C, int n) {
    constexpr int TNW = NOUT / 16;  // 4 or 8
    __shared__ float As[64 * 64];   // [k][row]
    __shared__ float Bs[64 * NOUT]; // [k][out]
    int tid = threadIdx.x;
    int row0 = blockIdx.x * 64;
    #pragma unroll
    for (int i = 0; i < 16; i++) {
        int idx = tid + 256 * i;
        int r = idx >> 6, k = idx & 63;
        float v = (row0 + r < n) ? A[(size_t)(row0 + r) * 64 + k] : 0.f;
        As[k * 64 + r] = v;
    }
    #pragma unroll
    for (int i = 0; i < 64 * NOUT / 256; i++) {
        int idx = tid + 256 * i;
        Bs[idx] = B[idx];
    }
    __syncthreads();
    int tm = tid >> 4, tn = tid & 15;
    float acc[4][TNW];
    #pragma unroll
    for (int i = 0; i < 4; i++)
        #pragma unroll
        for (int j = 0; j < TNW; j++) acc[i][j] = 0.f;
    #pragma unroll 4
    for (int k = 0; k < 64; k++) {
        float4 a = *(const float4*)&As[k * 64 + tm * 4];
        float b[TNW];
        *(float4*)&b[0] = *(const float4*)&Bs[k * NOUT + tn * TNW];
        if (TNW == 8) *(float4*)&b[4] = *(const float4*)&Bs[k * NOUT + tn * TNW + 4];
        float av[4] = {a.x, a.y, a.z, a.w};
        #pragma unroll
        for (int i = 0; i < 4; i++)
            #pragma unroll
            for (int j = 0; j < TNW; j++) acc[i][j] = fmaf(av[i], b[j], acc[i][j]);
    }
    #pragma unroll
    for (int i = 0; i < 4; i++) {
        int r = row0 + tm * 4 + i;
        if (r < n) {
            #pragma unroll
            for (int j = 0; j < TNW; j += 4)
                *(float4*)&C[(size_t)r * NOUT + tn * TNW + j] =
                    make_float4(acc[i][j], acc[i][j + 1], acc[i][j + 2], acc[i][j + 3]);
        }
    }
}

// ---------------- CSR gather-aggregate (no atomics), one warp per node ----------------
template <int F>
__global__ __launch_bounds__(256) void gather_kernel(const int* __restrict__ csr,
                                                     const int* __restrict__ offs,
                                                     const float* __restrict__ dinv,
                                                     const float* __restrict__ m,
                                                     float* __restrict__ agg, int n) {
    constexpr int VEC = F / 32;  // 2 or 4
    int node = (blockIdx.x * blockDim.x + threadIdx.x) >> 5;
    int lane = threadIdx.x & 31;
    if (node >= n) return;
    int beg = offs[node], end = offs[node + 1];
    float dc = dinv[node];
    float acc[VEC];
    #pragma unroll
    for (int v = 0; v < VEC; v++) acc[v] = 0.f;

    for (int i = beg; i < end; i += 32) {
        int idx = i + lane;
        int r = 0; float nd = 0.f;
        if (idx < end) { r = csr[idx]; nd = dinv[r]; }
        int cnt = min(32, end - i);
        int j = 0;
        for (; j + 4 <= cnt; j += 4) {
            int r0 = __shfl_sync(0xffffffffu, r, j);
            int r1 = __shfl_sync(0xffffffffu, r, j + 1);
            int r2 = __shfl_sync(0xffffffffu, r, j + 2);
            int r3 = __shfl_sync(0xffffffffu, r, j + 3);
            float n0 = __shfl_sync(0xffffffffu, nd, j) * dc;
            float n1 = __shfl_sync(0xffffffffu, nd, j + 1) * dc;
            float n2 = __shfl_sync(0xffffffffu, nd, j + 2) * dc;
            float n3 = __shfl_sync(0xffffffffu, nd, j + 3) * dc;
            if (VEC == 4) {
                float4 v0 = *(const float4*)&m[(size_t)r0 * F + lane * 4];
                float4 v1 = *(const float4*)&m[(size_t)r1 * F + lane * 4];
                float4 v2 = *(const float4*)&m[(size_t)r2 * F + lane * 4];
                float4 v3 = *(const float4*)&m[(size_t)r3 * F + lane * 4];
                acc[0] = fmaf(n0, v0.x, fmaf(n1, v1.x, fmaf(n2, v2.x, fmaf(n3, v3.x, acc[0]))));
                acc[1] = fmaf(n0, v0.y, fmaf(n1, v1.y, fmaf(n2, v2.y, fmaf(n3, v3.y, acc[1]))));
                acc[2] = fmaf(n0, v0.z, fmaf(n1, v1.z, fmaf(n2, v2.z, fmaf(n3, v3.z, acc[2]))));
                acc[3] = fmaf(n0, v0.w, fmaf(n1, v1.w, fmaf(n2, v2.w, fmaf(n3, v3.w, acc[3]))));
            } else {
                float2 v0 = *(const float2*)&m[(size_t)r0 * F + lane * 2];
                float2 v1 = *(const float2*)&m[(size_t)r1 * F + lane * 2];
                float2 v2 = *(const float2*)&m[(size_t)r2 * F + lane * 2];
                float2 v3 = *(const float2*)&m[(size_t)r3 * F + lane * 2];
                acc[0] = fmaf(n0, v0.x, fmaf(n1, v1.x, fmaf(n2, v2.x, fmaf(n3, v3.x, acc[0]))));
                acc[1] = fmaf(n0, v0.y, fmaf(n1, v1.y, fmaf(n2, v2.y, fmaf(n3, v3.y, acc[1]))));
            }
        }
        for (; j < cnt; j++) {
            int rr = __shfl_sync(0xffffffffu, r, j);
            float nn = __shfl_sync(0xffffffffu, nd, j) * dc;
            if (VEC == 4) {
                float4 v = *(const float4*)&m[(size_t)rr * F + lane * 4];
                acc[0] = fmaf(nn, v.x, acc[0]);
                acc[1] = fmaf(nn, v.y, acc[1]);
                acc[2] = fmaf(nn, v.z, acc[2]);
                acc[3] = fmaf(nn, v.w, acc[3]);
            } else {
                float2 v = *(const float2*)&m[(size_t)rr * F + lane * 2];
                acc[0] = fmaf(nn, v.x, acc[0]);
                acc[1] = fmaf(nn, v.y, acc[1]);
            }
        }
    }
    if (VEC == 4)
        *(float4*)&agg[(size_t)node * F + lane * 4] = make_float4(acc[0], acc[1], acc[2], acc[3]);
    else
        *(float2*)&agg[(size_t)node * F + lane * 2] = make_float2(acc[0], acc[1]);
}

// ---------------- BatchNorm statistics (per-channel sum & sumsq) ----------------
template <int F>
__global__ void stats_kernel(const float* __restrict__ agg, float* __restrict__ stats, int n) {
    constexpr int G = 256 / F;
    int c = threadIdx.x % F;
    int g = threadIdx.x / F;
    int base = blockIdx.x * 256;
    float s = 0.f, s2 = 0.f;
    for (int r = base + g; r < n && r < base + 256; r += G) {
        float v = agg[(size_t)r * F + c];
        s += v;
        s2 += v * v;
    }
    __shared__ float sm[256], sm2[256];
    sm[threadIdx.x] = s;
    sm2[threadIdx.x] = s2;
    __syncthreads();
    if (g == 0) {
        #pragma unroll
        for (int gg = 1; gg < G; gg++) {
            s += sm[gg * F + c];
            s2 += sm2[gg * F + c];
        }
        atomicAdd(&stats[c], s);
        atomicAdd(&stats[F + c], s2);
    }
}

// a = gamma * rsqrt(var+eps); shift = beta - a*mu  (GCN bias cancels in BN)
__global__ void finalize_kernel(const float* __restrict__ stats, const float* __restrict__ g,
                                const float* __restrict__ be, float* __restrict__ ab,
                                int n, int F) {
    int c = threadIdx.x;
    if (c < F) {
        float inv_n = 1.f / (float)n;
        float mu = stats[c] * inv_n;
        float var = fmaxf(stats[F + c] * inv_n - mu * mu, 0.f);
        float a = g[c] * rsqrtf(var + 1e-5f);
        ab[c] = a;
        ab[F + c] = be[c] - a * mu;
    }
}

// h1 = san(relu(a*agg + shift) + x)     (F=64)
__global__ void h1_kernel(const float* __restrict__ agg, const float* __restrict__ x,
                          const float* __restrict__ ab, float* __restrict__ h1, int total) {
    int i = blockIdx.x * blockDim.x + threadIdx.x;
    if (i < total) {
        int c = i & 63;
        float v = fmaf(ab[c], agg[i], ab[64 + c]);
        v = fmaxf(v, 0.f) + x[i];
        h1[i] = san(v);
    }
}

// out = san(a*agg + shift + proj)       (F=128)
__global__ void out_kernel(const float* __restrict__ agg, const float* __restrict__ proj,
                           const float* __restrict__ ab, float* __restrict__ out, int total) {
    int i = blockIdx.x * blockDim.x + threadIdx.x;
    if (i < total) {
        int c = i & 127;
        float v = fmaf(ab[c], agg[i], ab[128 + c]) + proj[i];
        out[i] = san(v);
    }
}

// ---------------- FC1: relu(concat(out0,out1) @ W[256,128] + b) ----------------
__global__ __launch_bounds__(256) void fc1_kernel(const float* __restrict__ A0,
                                                  const float* __restrict__ A1,
                                                  const float* __restrict__ B,
                                                  const float* __restrict__ bias,
                                                  float* __restrict__ H, int n) {
    __shared__ float As[64 * 64];
    __shared__ float Bs[64 * 128];
    int tid = threadIdx.x;
    int row0 = blockIdx.x * 64;
    int tm = tid >> 4, tn = tid & 15;
    float acc[4][8];
    #pragma unroll
    for (int i = 0; i < 4; i++)
        #pragma unroll
        for (int j = 0; j < 8; j++) acc[i][j] = 0.f;

    for (int c = 0; c < 4; c++) {
        __syncthreads();
        const float* Asrc = (c < 2) ? A0 : A1;
        int kbase = (c & 1) * 64;
        #pragma unroll
        for (int i = 0; i < 16; i++) {
            int idx = tid + 256 * i;
            int r = idx >> 6, kk = idx & 63;
            float v = (row0 + r < n) ? Asrc[(size_t)(row0 + r) * 128 + kbase + kk] : 0.f;
            As[kk * 64 + r] = v;
        }
        #pragma unroll
        for (int i = 0; i < 32; i++) {
            int idx = tid + 256 * i;
            Bs[idx] = B[c * 64 * 128 + idx];
        }
        __syncthreads();
        #pragma unroll 4
        for (int k = 0; k < 64; k++) {
            float4 a = *(const float4*)&As[k * 64 + tm * 4];
            float b[8];
            *(float4*)&b[0] = *(const float4*)&Bs[k * 128 + tn * 8];
            *(float4*)&b[4] = *(const float4*)&Bs[k * 128 + tn * 8 + 4];
            float av[4] = {a.x, a.y, a.z, a.w};
            #pragma unroll
            for (int i = 0; i < 4; i++)
                #pragma unroll
                for (int j = 0; j < 8; j++) acc[i][j] = fmaf(av[i], b[j], acc[i][j]);
        }
    }
    #pragma unroll
    for (int i = 0; i < 4; i++) {
        int r = row0 + tm * 4 + i;
        if (r < n) {
            #pragma unroll
            for (int j = 0; j < 8; j++) {
                float v = acc[i][j] + bias[tn * 8 + j];
                H[(size_t)r * 128 + tn * 8 + j] = fmaxf(v, 0.f);
            }
        }
    }
}

// ---------------- FC2 + softmax, one warp per node ----------------
__global__ void fc2_softmax_kernel(const float* __restrict__ H, const float* __restrict__ W2,
                                   const float* __restrict__ b2, float* __restrict__ out, int n) {
    int node = (blockIdx.x * blockDim.x + threadIdx.x) >> 5;
    int lane = threadIdx.x & 31;
    if (node >= n) return;
    float a0 = 0.f, a1 = 0.f;
    #pragma unroll
    for (int j = 0; j < 4; j++) {
        int k = lane + 32 * j;
        float h = H[(size_t)node * 128 + k];
        a0 = fmaf(h, W2[k * 2 + 0], a0);
        a1 = fmaf(h, W2[k * 2 + 1], a1);
    }
    #pragma unroll
    for (int off = 16; off; off >>= 1) {
        a0 += __shfl_xor_sync(0xffffffffu, a0, off);
        a1 += __shfl_xor_sync(0xffffffffu, a1, off);
    }
    if (lane == 0) {
        float l0 = a0 + b2[0], l1 = a1 + b2[1];
        float mx = fmaxf(l0, l1);
        float e0 = expf(l0 - mx), e1 = expf(l1 - mx);
        float inv = 1.f / (e0 + e1);
        out[(size_t)node * 2 + 0] = l0;
        out[(size_t)node * 2 + 1] = l1;
        out[(size_t)2 * n + node * 2 + 0] = e0 * inv;
        out[(size_t)2 * n + node * 2 + 1] = e1 * inv;
    }
}

// ---------------- host launch ----------------
extern "C" void kernel_launch(void* const* d_in, const int* in_sizes, int n_in,
                              void* d_out, int out_size) {
    const float* x    = (const float*)d_in[0];
    const int*   ei0  = (const int*)d_in[1];
    const int*   ei1  = (const int*)d_in[2];
    const float* w0[2]   = {(const float*)d_in[3], (const float*)d_in[8]};
    const float* w1[2]   = {(const float*)d_in[5], (const float*)d_in[10]};
    const float* res1[2] = {(const float*)d_in[7], (const float*)d_in[12]};
    const float* bn_g0 = (const float*)d_in[13];
    const float* bn_b0 = (const float*)d_in[14];
    const float* bn_g1 = (const float*)d_in[15];
    const float* bn_b1 = (const float*)d_in[16];
    const float* fc1_w = (const float*)d_in[17];
    const float* fc1_b = (const float*)d_in[18];
    const float* fc2_w = (const float*)d_in[19];
    const float* fc2_b = (const float*)d_in[20];

    int n = in_sizes[0] / 64;
    int E = in_sizes[1] / 2;

    float *dinv_p, *m_p, *agg_p, *proj_p, *h1_p, *hfc_p, *stats_p, *ab_p;
    float *outp[2];
    int *deg_p, *offs_p, *cursor_p, *csr_p;
    cudaGetSymbolAddress((void**)&dinv_p, g_dinv);
    cudaGetSymbolAddress((void**)&deg_p, g_deg);
    cudaGetSymbolAddress((void**)&offs_p, g_offs);
    cudaGetSymbolAddress((void**)&cursor_p, g_cursor);
    cudaGetSymbolAddress((void**)&csr_p, g_csr);
    cudaGetSymbolAddress((void**)&m_p, g_m);
    cudaGetSymbolAddress((void**)&agg_p, g_agg);
    cudaGetSymbolAddress((void**)&proj_p, g_proj);
    cudaGetSymbolAddress((void**)&h1_p, g_h1);
    cudaGetSymbolAddress((void**)&outp[0], g_out0);
    cudaGetSymbolAddress((void**)&outp[1], g_out1);
    cudaGetSymbolAddress((void**)&hfc_p, g_hfc);
    cudaGetSymbolAddress((void**)&stats_p, g_stats);
    cudaGetSymbolAddress((void**)&ab_p, g_ab);

    int ebl = (E + 255) / 256;
    int nbl = (n + 255) / 256;
    int gbl = (n + 63) / 64;      // gemm blocks (64 rows/block)
    int wbl = (n + 7) / 8;        // warp-per-node blocks (8 warps/block)

    for (int s = 0; s < 2; s++) {
        const int* row = s ? ei1 : ei0;
        const int* col = row + E;

        // degree + normalization + CSR build
        cudaMemsetAsync(deg_p, 0, n * sizeof(int));
        deg_kernel<<<ebl, 256>>>(col, deg_p, E);
        dinv_kernel<<<nbl, 256>>>(deg_p, dinv_p, n);
        scan_kernel<<<1, 1024>>>(deg_p, offs_p, cursor_p, n);
        csr_fill_kernel<<<ebl, 256>>>(row, col, cursor_p, csr_p, E);

        // layer 0: m = x @ W0 ; aggregate ; BN stats ; h1 = san(relu(bn)+x)
        sgemm64_kernel<64><<<gbl, 256>>>(x, w0[s], m_p, n);
        gather_kernel<64><<<wbl, 256>>>(csr_p, offs_p, dinv_p, m_p, agg_p, n);
        cudaMemsetAsync(stats_p, 0, 256 * sizeof(float));
        stats_kernel<64><<<nbl, 256>>>(agg_p, stats_p, n);
        finalize_kernel<<<1, 64>>>(stats_p, bn_g0, bn_b0, ab_p, n, 64);
        h1_kernel<<<(n * 64 + 255) / 256, 256>>>(agg_p, x, ab_p, h1_p, n * 64);

        // layer 1: m = h1 @ W1 ; proj = h1 @ res1 ; aggregate ; BN ; out_s
        sgemm64_kernel<128><<<gbl, 256>>>(h1_p, w1[s], m_p, n);
        sgemm64_kernel<128><<<gbl, 256>>>(h1_p, res1[s], proj_p, n);
        gather_kernel<128><<<wbl, 256>>>(csr_p, offs_p, dinv_p, m_p, agg_p, n);
        cudaMemsetAsync(stats_p, 0, 256 * sizeof(float));
        stats_kernel<128><<<nbl, 256>>>(agg_p, stats_p, n);
        finalize_kernel<<<1, 128>>>(stats_p, bn_g1, bn_b1, ab_p, n, 128);
        out_kernel<<<(n * 128 + 255) / 256, 256>>>(agg_p, proj_p, ab_p, outp[s], n * 128);
    }

    // head: fc1 (relu) -> fc2 -> softmax
    fc1_kernel<<<gbl, 256>>>(outp[0], outp[1], fc1_w, fc1_b, hfc_p, n);
    fc2_softmax_kernel<<<wbl, 256>>>(hfc_p, fc2_w, fc2_b, (float*)d_out, n);
}

// round 5
// speedup vs baseline: 1.1923x; 1.1923x over previous
#include <cuda_runtime.h>
#include <cuda_bf16.h>
#include <math.h>

#define MAXN 50048
#define MAXE 1600000

// ---------------- per-slice device scratch (static; no allocations) ----------------
__device__ __align__(16) float g_dinv[2][MAXN];
__device__ __align__(16) int   g_deg[2][MAXN];
__device__ __align__(16) int   g_offs[2][MAXN + 1];
__device__ __align__(16) int   g_cursor[2][MAXN];
__device__ __align__(16) int   g_csr[2][MAXE];
__device__ __align__(16) float g_m[2][(size_t)MAXN * 128];
__device__ __align__(16) float g_agg0[2][(size_t)MAXN * 64];
__device__ __align__(16) float g_agg1[2][(size_t)MAXN * 128];
__device__ __align__(16) float g_proj[2][(size_t)MAXN * 128];
__device__ __align__(16) float g_stats0[2][128];
__device__ __align__(16) float g_stats1[2][256];
__device__ __align__(16) float g_ab0[2][128];
__device__ __align__(16) float g_ab1[2][256];
__device__ __align__(16) float g_hfc[(size_t)MAXN * 128];

// ---------------- static streams / events (host-side, created at load) ----------------
static cudaStream_t g_str[4];
static cudaEvent_t  g_ev[10];
static int g_init_streams = []() {
    for (int i = 0; i < 4; i++) cudaStreamCreateWithFlags(&g_str[i], cudaStreamNonBlocking);
    for (int i = 0; i < 10; i++) cudaEventCreateWithFlags(&g_ev[i], cudaEventDisableTiming);
    return 0;
}();

// nan_to_num(nan=0, posinf=100, neginf=-100)
__device__ __forceinline__ float san(float v) {
    if (isnan(v)) return 0.f;
    if (isinf(v)) return v > 0.f ? 100.f : -100.f;
    return v;
}

// ---------------- degree ----------------
__global__ void deg_kernel(const int* __restrict__ col, int* __restrict__ deg, int E) {
    int e = blockIdx.x * blockDim.x + threadIdx.x;
    if (e < E) atomicAdd(&deg[col[e]], 1);
}

// single-block exclusive scan of deg -> offs/cursor, plus fused dinv = rsqrt(deg)
__global__ void scan_kernel(const int* __restrict__ deg, int* __restrict__ offs,
                            int* __restrict__ cursor, float* __restrict__ dinv, int n) {
    __shared__ int wsum[32];
    __shared__ int carry_s;
    int tid = threadIdx.x;
    int lane = tid & 31, wid = tid >> 5;
    if (tid == 0) carry_s = 0;
    __syncthreads();
    int nIter = (n + 1023) >> 10;
    for (int it = 0; it < nIter; it++) {
        int i = (it << 10) + tid;
        int v = (i < n) ? deg[i] : 0;
        if (i < n) dinv[i] = v > 0 ? rsqrtf((float)v) : 0.f;
        int x = v;
        #pragma unroll
        for (int off = 1; off < 32; off <<= 1) {
            int y = __shfl_up_sync(0xffffffffu, x, off);
            if (lane >= off) x += y;
        }
        if (lane == 31) wsum[wid] = x;
        __syncthreads();
        if (wid == 0) {
            int w = wsum[lane];
            #pragma unroll
            for (int off = 1; off < 32; off <<= 1) {
                int y = __shfl_up_sync(0xffffffffu, w, off);
                if (lane >= off) w += y;
            }
            wsum[lane] = w;
        }
        __syncthreads();
        int pre = (wid > 0) ? wsum[wid - 1] : 0;
        int total = wsum[31];
        int excl = carry_s + pre + x - v;
        if (i < n) { offs[i] = excl; cursor[i] = excl; }
        __syncthreads();
        if (tid == 0) carry_s += total;
        __syncthreads();
    }
    if (tid == 0) offs[n] = carry_s;
}

__global__ void csr_fill_kernel(const int* __restrict__ row, const int* __restrict__ col,
                                int* __restrict__ cursor, int* __restrict__ csr, int E) {
    int e = blockIdx.x * blockDim.x + threadIdx.x;
    if (e < E) {
        int pos = atomicAdd(&cursor[col[e]], 1);
        csr[pos] = row[e];
    }
}

// ---------------- register-tiled SGEMM: C[n,NOUT] = A'[n,64] @ B[64,NOUT] ----------------
// FUSE_H1: A'[r,k] = san(relu(ab[k]*agg[r,k] + ab[64+k]) + x[r,k]) instead of raw A.
template <int NOUT, bool FUSE_H1>
__global__ __launch_bounds__(256) void sgemm64_kernel(const float* __restrict__ A,
                                                      const float* __restrict__ X,
                                                      const float* __restrict__ ab,
                                                      const float* __restrict__ B,
                                                      float* __restrict__ C, int n) {
    constexpr int TNW = NOUT / 16;  // 4 or 8
    __shared__ float As[64 * 64];   // [k][row]
    __shared__ float Bs[64 * NOUT]; // [k][out]
    int tid = threadIdx.x;
    int row0 = blockIdx.x * 64;
    #pragma unroll
    for (int i = 0; i < 16; i++) {
        int idx = tid + 256 * i;
        int r = idx >> 6, k = idx & 63;
        float v = 0.f;
        if (row0 + r < n) {
            size_t o = (size_t)(row0 + r) * 64 + k;
            if (FUSE_H1) {
                float t = fmaf(ab[k], A[o], ab[64 + k]);
                v = san(fmaxf(t, 0.f) + X[o]);
            } else {
                v = A[o];
            }
        }
        As[k * 64 + r] = v;
    }
    #pragma unroll
    for (int i = 0; i < 64 * NOUT / 256; i++) {
        int idx = tid + 256 * i;
        Bs[idx] = B[idx];
    }
    __syncthreads();
    int tm = tid >> 4, tn = tid & 15;
    float acc[4][TNW];
    #pragma unroll
    for (int i = 0; i < 4; i++)
        #pragma unroll
        for (int j = 0; j < TNW; j++) acc[i][j] = 0.f;
    #pragma unroll 4
    for (int k = 0; k < 64; k++) {
        float4 a = *(const float4*)&As[k * 64 + tm * 4];
        float b[TNW];
        *(float4*)&b[0] = *(const float4*)&Bs[k * NOUT + tn * TNW];
        if (TNW == 8) *(float4*)&b[4] = *(const float4*)&Bs[k * NOUT + tn * TNW + 4];
        float av[4] = {a.x, a.y, a.z, a.w};
        #pragma unroll
        for (int i = 0; i < 4; i++)
            #pragma unroll
            for (int j = 0; j < TNW; j++) acc[i][j] = fmaf(av[i], b[j], acc[i][j]);
    }
    #pragma unroll
    for (int i = 0; i < 4; i++) {
        int r = row0 + tm * 4 + i;
        if (r < n) {
            #pragma unroll
            for (int j = 0; j < TNW; j += 4)
                *(float4*)&C[(size_t)r * NOUT + tn * TNW + j] =
                    make_float4(acc[i][j], acc[i][j + 1], acc[i][j + 2], acc[i][j + 3]);
        }
    }
}

// ---------------- CSR gather-aggregate with fused BN statistics ----------------
template <int F>
__global__ __launch_bounds__(256) void gather_kernel(const int* __restrict__ csr,
                                                     const int* __restrict__ offs,
                                                     const float* __restrict__ dinv,
                                                     const float* __restrict__ m,
                                                     float* __restrict__ agg,
                                                     float* __restrict__ stats, int n) {
    constexpr int VEC = F / 32;  // 2 or 4
    __shared__ float ssum[F], ssq[F];
    if (threadIdx.x < F) { ssum[threadIdx.x] = 0.f; ssq[threadIdx.x] = 0.f; }
    __syncthreads();

    int node = (blockIdx.x * blockDim.x + threadIdx.x) >> 5;
    int lane = threadIdx.x & 31;
    float acc[VEC];
    #pragma unroll
    for (int v = 0; v < VEC; v++) acc[v] = 0.f;

    if (node < n) {
        int beg = offs[node], end = offs[node + 1];
        float dc = dinv[node];
        for (int i = beg; i < end; i += 32) {
            int idx = i + lane;
            int r = 0; float nd = 0.f;
            if (idx < end) { r = csr[idx]; nd = dinv[r]; }
            int cnt = min(32, end - i);
            int j = 0;
            for (; j + 4 <= cnt; j += 4) {
                int r0 = __shfl_sync(0xffffffffu, r, j);
                int r1 = __shfl_sync(0xffffffffu, r, j + 1);
                int r2 = __shfl_sync(0xffffffffu, r, j + 2);
                int r3 = __shfl_sync(0xffffffffu, r, j + 3);
                float n0 = __shfl_sync(0xffffffffu, nd, j) * dc;
                float n1 = __shfl_sync(0xffffffffu, nd, j + 1) * dc;
                float n2 = __shfl_sync(0xffffffffu, nd, j + 2) * dc;
                float n3 = __shfl_sync(0xffffffffu, nd, j + 3) * dc;
                if (VEC == 4) {
                    float4 v0 = *(const float4*)&m[(size_t)r0 * F + lane * 4];
                    float4 v1 = *(const float4*)&m[(size_t)r1 * F + lane * 4];
                    float4 v2 = *(const float4*)&m[(size_t)r2 * F + lane * 4];
                    float4 v3 = *(const float4*)&m[(size_t)r3 * F + lane * 4];
                    acc[0] = fmaf(n0, v0.x, fmaf(n1, v1.x, fmaf(n2, v2.x, fmaf(n3, v3.x, acc[0]))));
                    acc[1] = fmaf(n0, v0.y, fmaf(n1, v1.y, fmaf(n2, v2.y, fmaf(n3, v3.y, acc[1]))));
                    acc[2] = fmaf(n0, v0.z, fmaf(n1, v1.z, fmaf(n2, v2.z, fmaf(n3, v3.z, acc[2]))));
                    acc[3] = fmaf(n0, v0.w, fmaf(n1, v1.w, fmaf(n2, v2.w, fmaf(n3, v3.w, acc[3]))));
                } else {
                    float2 v0 = *(const float2*)&m[(size_t)r0 * F + lane * 2];
                    float2 v1 = *(const float2*)&m[(size_t)r1 * F + lane * 2];
                    float2 v2 = *(const float2*)&m[(size_t)r2 * F + lane * 2];
                    float2 v3 = *(const float2*)&m[(size_t)r3 * F + lane * 2];
                    acc[0] = fmaf(n0, v0.x, fmaf(n1, v1.x, fmaf(n2, v2.x, fmaf(n3, v3.x, acc[0]))));
                    acc[1] = fmaf(n0, v0.y, fmaf(n1, v1.y, fmaf(n2, v2.y, fmaf(n3, v3.y, acc[1]))));
                }
            }
            for (; j < cnt; j++) {
                int rr = __shfl_sync(0xffffffffu, r, j);
                float nn = __shfl_sync(0xffffffffu, nd, j) * dc;
                if (VEC == 4) {
                    float4 v = *(const float4*)&m[(size_t)rr * F + lane * 4];
                    acc[0] = fmaf(nn, v.x, acc[0]);
                    acc[1] = fmaf(nn, v.y, acc[1]);
                    acc[2] = fmaf(nn, v.z, acc[2]);
                    acc[3] = fmaf(nn, v.w, acc[3]);
                } else {
                    float2 v = *(const float2*)&m[(size_t)rr * F + lane * 2];
                    acc[0] = fmaf(nn, v.x, acc[0]);
                    acc[1] = fmaf(nn, v.y, acc[1]);
                }
            }
        }
        if (VEC == 4)
            *(float4*)&agg[(size_t)node * F + lane * 4] = make_float4(acc[0], acc[1], acc[2], acc[3]);
        else
            *(float2*)&agg[(size_t)node * F + lane * 2] = make_float2(acc[0], acc[1]);
    }

    // fused BN statistics: block-reduce then one global atomic per channel
    #pragma unroll
    for (int v = 0; v < VEC; v++) {
        int c = lane * VEC + v;
        atomicAdd(&ssum[c], acc[v]);
        atomicAdd(&ssq[c], acc[v] * acc[v]);
    }
    __syncthreads();
    if (threadIdx.x < F) {
        atomicAdd(&stats[threadIdx.x], ssum[threadIdx.x]);
        atomicAdd(&stats[F + threadIdx.x], ssq[threadIdx.x]);
    }
}

// a = gamma * rsqrt(var+eps); shift = beta - a*mu  (GCN bias cancels in BN)
__global__ void finalize_kernel(const float* __restrict__ stats, const float* __restrict__ g,
                                const float* __restrict__ be, float* __restrict__ ab,
                                int n, int F) {
    int c = threadIdx.x;
    if (c < F) {
        float inv_n = 1.f / (float)n;
        float mu = stats[c] * inv_n;
        float var = fmaxf(stats[F + c] * inv_n - mu * mu, 0.f);
        float a = g[c] * rsqrtf(var + 1e-5f);
        ab[c] = a;
        ab[F + c] = be[c] - a * mu;
    }
}

// ---------------- FC1 with fused layer-1 epilogue on the A side ----------------
// A'[r, s*128 + k] = san(ab1_s[k]*agg1_s[r,k] + ab1_s[128+k] + proj_s[r,k])
__global__ __launch_bounds__(256) void fc1_kernel(const float* __restrict__ agg0,
                                                  const float* __restrict__ proj0,
                                                  const float* __restrict__ ab_0,
                                                  const float* __restrict__ agg1,
                                                  const float* __restrict__ proj1,
                                                  const float* __restrict__ ab_1,
                                                  const float* __restrict__ B,
                                                  const float* __restrict__ bias,
                                                  float* __restrict__ H, int n) {
    __shared__ float As[64 * 64];
    __shared__ float Bs[64 * 128];
    int tid = threadIdx.x;
    int row0 = blockIdx.x * 64;
    int tm = tid >> 4, tn = tid & 15;
    float acc[4][8];
    #pragma unroll
    for (int i = 0; i < 4; i++)
        #pragma unroll
        for (int j = 0; j < 8; j++) acc[i][j] = 0.f;

    for (int c = 0; c < 4; c++) {
        __syncthreads();
        const float* agg = (c < 2) ? agg0 : agg1;
        const float* prj = (c < 2) ? proj0 : proj1;
        const float* ab  = (c < 2) ? ab_0 : ab_1;
        int kbase = (c & 1) * 64;
        #pragma unroll
        for (int i = 0; i < 16; i++) {
            int idx = tid + 256 * i;
            int r = idx >> 6, kk = idx & 63;
            float v = 0.f;
            if (row0 + r < n) {
                int ch = kbase + kk;
                size_t o = (size_t)(row0 + r) * 128 + ch;
                v = san(fmaf(ab[ch], agg[o], ab[128 + ch]) + prj[o]);
            }
            As[kk * 64 + r] = v;
        }
        #pragma unroll
        for (int i = 0; i < 32; i++) {
            int idx = tid + 256 * i;
            Bs[idx] = B[c * 64 * 128 + idx];
        }
        __syncthreads();
        #pragma unroll 4
        for (int k = 0; k < 64; k++) {
            float4 a = *(const float4*)&As[k * 64 + tm * 4];
            float b[8];
            *(float4*)&b[0] = *(const float4*)&Bs[k * 128 + tn * 8];
            *(float4*)&b[4] = *(const float4*)&Bs[k * 128 + tn * 8 + 4];
            float av[4] = {a.x, a.y, a.z, a.w};
            #pragma unroll
            for (int i = 0; i < 4; i++)
                #pragma unroll
                for (int j = 0; j < 8; j++) acc[i][j] = fmaf(av[i], b[j], acc[i][j]);
        }
    }
    #pragma unroll
    for (int i = 0; i < 4; i++) {
        int r = row0 + tm * 4 + i;
        if (r < n) {
            #pragma unroll
            for (int j = 0; j < 8; j++) {
                float v = acc[i][j] + bias[tn * 8 + j];
                H[(size_t)r * 128 + tn * 8 + j] = fmaxf(v, 0.f);
            }
        }
    }
}

// ---------------- FC2 + softmax, one warp per node ----------------
__global__ void fc2_softmax_kernel(const float* __restrict__ H, const float* __restrict__ W2,
                                   const float* __restrict__ b2, float* __restrict__ out, int n) {
    int node = (blockIdx.x * blockDim.x + threadIdx.x) >> 5;
    int lane = threadIdx.x & 31;
    if (node >= n) return;
    float a0 = 0.f, a1 = 0.f;
    #pragma unroll
    for (int j = 0; j < 4; j++) {
        int k = lane + 32 * j;
        float h = H[(size_t)node * 128 + k];
        a0 = fmaf(h, W2[k * 2 + 0], a0);
        a1 = fmaf(h, W2[k * 2 + 1], a1);
    }
    #pragma unroll
    for (int off = 16; off; off >>= 1) {
        a0 += __shfl_xor_sync(0xffffffffu, a0, off);
        a1 += __shfl_xor_sync(0xffffffffu, a1, off);
    }
    if (lane == 0) {
        float l0 = a0 + b2[0], l1 = a1 + b2[1];
        float mx = fmaxf(l0, l1);
        float e0 = expf(l0 - mx), e1 = expf(l1 - mx);
        float inv = 1.f / (e0 + e1);
        out[(size_t)node * 2 + 0] = l0;
        out[(size_t)node * 2 + 1] = l1;
        out[(size_t)2 * n + node * 2 + 0] = e0 * inv;
        out[(size_t)2 * n + node * 2 + 1] = e1 * inv;
    }
}

// ---------------- host launch (fork-join multi-stream, graph-capturable) ----------------
extern "C" void kernel_launch(void* const* d_in, const int* in_sizes, int n_in,
                              void* d_out, int out_size) {
    const float* x     = (const float*)d_in[0];
    const int*   ei[2] = {(const int*)d_in[1], (const int*)d_in[2]};
    const float* w0[2]   = {(const float*)d_in[3], (const float*)d_in[8]};
    const float* w1[2]   = {(const float*)d_in[5], (const float*)d_in[10]};
    const float* res1[2] = {(const float*)d_in[7], (const float*)d_in[12]};
    const float* bn_g0 = (const float*)d_in[13];
    const float* bn_b0 = (const float*)d_in[14];
    const float* bn_g1 = (const float*)d_in[15];
    const float* bn_b1 = (const float*)d_in[16];
    const float* fc1_w = (const float*)d_in[17];
    const float* fc1_b = (const float*)d_in[18];
    const float* fc2_w = (const float*)d_in[19];
    const float* fc2_b = (const float*)d_in[20];

    int n = in_sizes[0] / 64;
    int E = in_sizes[1] / 2;

    float *dinv_p[2], *m_p[2], *agg0_p[2], *agg1_p[2], *proj_p[2];
    float *stats0_p[2], *stats1_p[2], *ab0_p[2], *ab1_p[2], *hfc_p;
    int *deg_p[2], *offs_p[2], *cursor_p[2], *csr_p[2];
    {
        char* base;
        cudaGetSymbolAddress((void**)&base, g_dinv);
        dinv_p[0] = (float*)base; dinv_p[1] = dinv_p[0] + MAXN;
        cudaGetSymbolAddress((void**)&base, g_deg);
        deg_p[0] = (int*)base; deg_p[1] = deg_p[0] + MAXN;
        cudaGetSymbolAddress((void**)&base, g_offs);
        offs_p[0] = (int*)base; offs_p[1] = offs_p[0] + MAXN + 1;
        cudaGetSymbolAddress((void**)&base, g_cursor);
        cursor_p[0] = (int*)base; cursor_p[1] = cursor_p[0] + MAXN;
        cudaGetSymbolAddress((void**)&base, g_csr);
        csr_p[0] = (int*)base; csr_p[1] = csr_p[0] + MAXE;
        cudaGetSymbolAddress((void**)&base, g_m);
        m_p[0] = (float*)base; m_p[1] = m_p[0] + (size_t)MAXN * 128;
        cudaGetSymbolAddress((void**)&base, g_agg0);
        agg0_p[0] = (float*)base; agg0_p[1] = agg0_p[0] + (size_t)MAXN * 64;
        cudaGetSymbolAddress((void**)&base, g_agg1);
        agg1_p[0] = (float*)base; agg1_p[1] = agg1_p[0] + (size_t)MAXN * 128;
        cudaGetSymbolAddress((void**)&base, g_proj);
        proj_p[0] = (float*)base; proj_p[1] = proj_p[0] + (size_t)MAXN * 128;
        cudaGetSymbolAddress((void**)&base, g_stats0);
        stats0_p[0] = (float*)base; stats0_p[1] = stats0_p[0] + 128;
        cudaGetSymbolAddress((void**)&base, g_stats1);
        stats1_p[0] = (float*)base; stats1_p[1] = stats1_p[0] + 256;
        cudaGetSymbolAddress((void**)&base, g_ab0);
        ab0_p[0] = (float*)base; ab0_p[1] = ab0_p[0] + 128;
        cudaGetSymbolAddress((void**)&base, g_ab1);
        ab1_p[0] = (float*)base; ab1_p[1] = ab1_p[0] + 256;
        cudaGetSymbolAddress((void**)&hfc_p, g_hfc);
    }

    int ebl = (E + 255) / 256;
    int gbl = (n + 63) / 64;   // gemm blocks (64 rows/block)
    int wbl = (n + 7) / 8;     // warp-per-node blocks (8 warps/block)

    // events: 0 root; per slice s: 1+4s..4+4s = {gemm0 done, finalize0 done, projB done, slice done}
    cudaEventRecord(g_ev[0], 0);

    for (int s = 0; s < 2; s++) {
        const int* row = ei[s];
        const int* col = row + E;
        cudaStream_t a = g_str[2 * s];
        cudaStream_t b = g_str[2 * s + 1];
        cudaEvent_t evGemm0 = g_ev[1 + 4 * s];
        cudaEvent_t evFin0  = g_ev[2 + 4 * s];
        cudaEvent_t evProj  = g_ev[3 + 4 * s];
        cudaEvent_t evDone  = g_ev[4 + 4 * s];

        cudaStreamWaitEvent(a, g_ev[0], 0);
        cudaStreamWaitEvent(b, g_ev[0], 0);

        // stream b: stats zeroing + layer-0 transform GEMM (independent of CSR)
        cudaMemsetAsync(stats0_p[s], 0, 128 * sizeof(float), b);
        cudaMemsetAsync(stats1_p[s], 0, 256 * sizeof(float), b);
        sgemm64_kernel<64, false><<<gbl, 256, 0, b>>>(x, nullptr, nullptr, w0[s], m_p[s], n);
        cudaEventRecord(evGemm0, b);

        // stream a: CSR build chain
        cudaMemsetAsync(deg_p[s], 0, n * sizeof(int), a);
        deg_kernel<<<ebl, 256, 0, a>>>(col, deg_p[s], E);
        scan_kernel<<<1, 1024, 0, a>>>(deg_p[s], offs_p[s], cursor_p[s], dinv_p[s], n);
        csr_fill_kernel<<<ebl, 256, 0, a>>>(row, col, cursor_p[s], csr_p[s], E);

        // join: gather layer 0 (fused BN stats), finalize BN0
        cudaStreamWaitEvent(a, evGemm0, 0);
        gather_kernel<64><<<wbl, 256, 0, a>>>(csr_p[s], offs_p[s], dinv_p[s], m_p[s],
                                              agg0_p[s], stats0_p[s], n);
        finalize_kernel<<<1, 64, 0, a>>>(stats0_p[s], bn_g0, bn_b0, ab0_p[s], n, 64);
        cudaEventRecord(evFin0, a);

        // layer 1: m = h1' @ W1 on a (gather depends on it);
        //          proj = h1' @ res1 on b (only fc1 depends on it)
        sgemm64_kernel<128, true><<<gbl, 256, 0, a>>>(agg0_p[s], x, ab0_p[s], w1[s], m_p[s], n);
        cudaStreamWaitEvent(b, evFin0, 0);
        sgemm64_kernel<128, true><<<gbl, 256, 0, b>>>(agg0_p[s], x, ab0_p[s], res1[s], proj_p[s], n);
        cudaEventRecord(evProj, b);

        gather_kernel<128><<<wbl, 256, 0, a>>>(csr_p[s], offs_p[s], dinv_p[s], m_p[s],
                                               agg1_p[s], stats1_p[s], n);
        finalize_kernel<<<1, 128, 0, a>>>(stats1_p[s], bn_g1, bn_b1, ab1_p[s], n, 128);
        cudaStreamWaitEvent(a, evProj, 0);
        cudaEventRecord(evDone, a);
    }

    // join both slices back to origin stream; head
    cudaStreamWaitEvent(0, g_ev[4], 0);
    cudaStreamWaitEvent(0, g_ev[8], 0);
    fc1_kernel<<<gbl, 256>>>(agg1_p[0], proj_p[0], ab1_p[0],
                             agg1_p[1], proj_p[1], ab1_p[1],
                             fc1_w, fc1_b, hfc_p, n);
    fc2_softmax_kernel<<<wbl, 256>>>(hfc_p, fc2_w, fc2_b, (float*)d_out, n);
}

// round 6
// speedup vs baseline: 1.2935x; 1.0850x over previous
#include <cuda_runtime.h>
#include <cuda_bf16.h>
#include <cuda_fp16.h>
#include <math.h>

#define MAXN 50048           // divisible by 16
#define MAXNO (MAXN + 16)    // offs row stride, keeps slice-1 16B-aligned
#define MAXE 1600000

// ---------------- per-slice device scratch (static; no allocations) ----------------
__device__ __align__(16) float  g_dinv[2][MAXN];
__device__ __align__(16) int    g_deg[2][MAXN];
__device__ __align__(16) int    g_offs[2][MAXNO];
__device__ __align__(16) int    g_cursor[2][MAXN];
__device__ __align__(16) int    g_csr[2][MAXE];
__device__ __align__(16) __half g_m[2][(size_t)MAXN * 128];     // fp16 transformed features
__device__ __align__(16) float  g_agg0[2][(size_t)MAXN * 64];
__device__ __align__(16) float  g_agg1[2][(size_t)MAXN * 128];
__device__ __align__(16) float  g_proj[2][(size_t)MAXN * 128];
__device__ __align__(16) float  g_stats0[2][128];
__device__ __align__(16) float  g_stats1[2][256];
__device__ __align__(16) float  g_ab0[2][128];
__device__ __align__(16) float  g_ab1[2][256];
__device__ __align__(16) float  g_hfc[(size_t)MAXN * 128];

// ---------------- static streams / events (host-side, created at load) ----------------
static cudaStream_t g_str[4];
static cudaEvent_t  g_ev[10];
static int g_init_streams = []() {
    for (int i = 0; i < 4; i++) cudaStreamCreateWithFlags(&g_str[i], cudaStreamNonBlocking);
    for (int i = 0; i < 10; i++) cudaEventCreateWithFlags(&g_ev[i], cudaEventDisableTiming);
    return 0;
}();

// nan_to_num(nan=0, posinf=100, neginf=-100)
__device__ __forceinline__ float san(float v) {
    if (isnan(v)) return 0.f;
    if (isinf(v)) return v > 0.f ? 100.f : -100.f;
    return v;
}

__device__ __forceinline__ float4 ldh4(const __half* p) {
    uint2 w = *(const uint2*)p;
    float2 a = __half22float2(*(__half2*)&w.x);
    float2 b = __half22float2(*(__half2*)&w.y);
    return make_float4(a.x, a.y, b.x, b.y);
}
__device__ __forceinline__ float2 ldh2(const __half* p) {
    return __half22float2(*(const __half2*)p);
}

// ---------------- degree ----------------
__global__ void deg_kernel(const int* __restrict__ col, int* __restrict__ deg, int E) {
    int e = blockIdx.x * blockDim.x + threadIdx.x;
    if (e < E) atomicAdd(&deg[col[e]], 1);
}

// single-block exclusive scan (x4 vectorized) -> offs/cursor + fused dinv = rsqrt(deg)
__global__ void scan_kernel(const int* __restrict__ deg, int* __restrict__ offs,
                            int* __restrict__ cursor, float* __restrict__ dinv, int n) {
    __shared__ int wsum[32];
    __shared__ int carry_s;
    int tid = threadIdx.x;
    int lane = tid & 31, wid = tid >> 5;
    if (tid == 0) carry_s = 0;
    __syncthreads();
    int nIter = (n + 4095) >> 12;
    for (int it = 0; it < nIter; it++) {
        int i0 = (it << 12) + tid * 4;
        int v0 = 0, v1 = 0, v2 = 0, v3 = 0;
        if (i0 + 3 < n) {
            int4 t = *(const int4*)(deg + i0);
            v0 = t.x; v1 = t.y; v2 = t.z; v3 = t.w;
        } else {
            if (i0 < n)     v0 = deg[i0];
            if (i0 + 1 < n) v1 = deg[i0 + 1];
            if (i0 + 2 < n) v2 = deg[i0 + 2];
            if (i0 + 3 < n) v3 = deg[i0 + 3];
        }
        int s = v0 + v1 + v2 + v3;
        int x = s;
        #pragma unroll
        for (int off = 1; off < 32; off <<= 1) {
            int y = __shfl_up_sync(0xffffffffu, x, off);
            if (lane >= off) x += y;
        }
        if (lane == 31) wsum[wid] = x;
        __syncthreads();
        if (wid == 0) {
            int w = wsum[lane];
            #pragma unroll
            for (int off = 1; off < 32; off <<= 1) {
                int y = __shfl_up_sync(0xffffffffu, w, off);
                if (lane >= off) w += y;
            }
            wsum[lane] = w;
        }
        __syncthreads();
        int pre = (wid > 0) ? wsum[wid - 1] : 0;
        int total = wsum[31];
        int e0 = carry_s + pre + x - s;
        int o1 = e0 + v0, o2 = o1 + v1, o3 = o2 + v2;
        if (i0 + 3 < n) {
            *(int4*)(offs + i0)   = make_int4(e0, o1, o2, o3);
            *(int4*)(cursor + i0) = make_int4(e0, o1, o2, o3);
            float4 dv = make_float4(v0 > 0 ? rsqrtf((float)v0) : 0.f,
                                    v1 > 0 ? rsqrtf((float)v1) : 0.f,
                                    v2 > 0 ? rsqrtf((float)v2) : 0.f,
                                    v3 > 0 ? rsqrtf((float)v3) : 0.f);
            *(float4*)(dinv + i0) = dv;
        } else {
            int oo[4] = {e0, o1, o2, o3};
            int vv[4] = {v0, v1, v2, v3};
            for (int j = 0; j < 4; j++) {
                if (i0 + j < n) {
                    offs[i0 + j] = oo[j];
                    cursor[i0 + j] = oo[j];
                    dinv[i0 + j] = vv[j] > 0 ? rsqrtf((float)vv[j]) : 0.f;
                }
            }
        }
        __syncthreads();
        if (tid == 0) carry_s += total;
        __syncthreads();
    }
    if (tid == 0) offs[n] = carry_s;
}

__global__ void csr_fill_kernel(const int* __restrict__ row, const int* __restrict__ col,
                                int* __restrict__ cursor, int* __restrict__ csr, int E) {
    int e = blockIdx.x * blockDim.x + threadIdx.x;
    if (e < E) {
        int pos = atomicAdd(&cursor[col[e]], 1);
        csr[pos] = row[e];
    }
}

// ---------------- register-tiled SGEMM: C[n,NOUT] = A'[n,64] @ B[64,NOUT] ----------------
// FUSE_H1: A'[r,k] = san(relu(ab[k]*agg[r,k] + ab[64+k]) + x[r,k]).
// OUT_HALF: C stored as fp16, else fp32.
template <int NOUT, bool FUSE_H1, bool OUT_HALF>
__global__ __launch_bounds__(256) void sgemm64_kernel(const float* __restrict__ A,
                                                      const float* __restrict__ X,
                                                      const float* __restrict__ ab,
                                                      const float* __restrict__ B,
                                                      void* __restrict__ C, int n) {
    constexpr int TNW = NOUT / 16;  // 4 or 8
    __shared__ float As[64 * 64];   // [k][row]
    __shared__ float Bs[64 * NOUT]; // [k][out]
    int tid = threadIdx.x;
    int row0 = blockIdx.x * 64;
    #pragma unroll
    for (int i = 0; i < 16; i++) {
        int idx = tid + 256 * i;
        int r = idx >> 6, k = idx & 63;
        float v = 0.f;
        if (row0 + r < n) {
            unsigned o = (unsigned)(row0 + r) * 64u + k;
            if (FUSE_H1) {
                float t = fmaf(ab[k], A[o], ab[64 + k]);
                v = san(fmaxf(t, 0.f) + X[o]);
            } else {
                v = A[o];
            }
        }
        As[k * 64 + r] = v;
    }
    #pragma unroll
    for (int i = 0; i < 64 * NOUT / 256; i++) {
        int idx = tid + 256 * i;
        Bs[idx] = B[idx];
    }
    __syncthreads();
    int tm = tid >> 4, tn = tid & 15;
    float acc[4][TNW];
    #pragma unroll
    for (int i = 0; i < 4; i++)
        #pragma unroll
        for (int j = 0; j < TNW; j++) acc[i][j] = 0.f;
    #pragma unroll 4
    for (int k = 0; k < 64; k++) {
        float4 a = *(const float4*)&As[k * 64 + tm * 4];
        float b[TNW];
        *(float4*)&b[0] = *(const float4*)&Bs[k * NOUT + tn * TNW];
        if (TNW == 8) *(float4*)&b[4] = *(const float4*)&Bs[k * NOUT + tn * TNW + 4];
        float av[4] = {a.x, a.y, a.z, a.w};
        #pragma unroll
        for (int i = 0; i < 4; i++)
            #pragma unroll
            for (int j = 0; j < TNW; j++) acc[i][j] = fmaf(av[i], b[j], acc[i][j]);
    }
    #pragma unroll
    for (int i = 0; i < 4; i++) {
        int r = row0 + tm * 4 + i;
        if (r < n) {
            if (OUT_HALF) {
                __half* Ch = (__half*)C;
                #pragma unroll
                for (int j = 0; j < TNW; j += 4) {
                    __half2 p0 = __floats2half2_rn(acc[i][j], acc[i][j + 1]);
                    __half2 p1 = __floats2half2_rn(acc[i][j + 2], acc[i][j + 3]);
                    uint2 w;
                    w.x = *(unsigned*)&p0;
                    w.y = *(unsigned*)&p1;
                    *(uint2*)&Ch[(unsigned)r * NOUT + tn * TNW + j] = w;
                }
            } else {
                float* Cf = (float*)C;
                #pragma unroll
                for (int j = 0; j < TNW; j += 4)
                    *(float4*)&Cf[(unsigned)r * NOUT + tn * TNW + j] =
                        make_float4(acc[i][j], acc[i][j + 1], acc[i][j + 2], acc[i][j + 3]);
            }
        }
    }
}

// ---------------- CSR gather-aggregate (fp16 source) with fused BN statistics ----------------
template <int F>
__global__ __launch_bounds__(256) void gather_kernel(const int* __restrict__ csr,
                                                     const int* __restrict__ offs,
                                                     const float* __restrict__ dinv,
                                                     const __half* __restrict__ m,
                                                     float* __restrict__ agg,
                                                     float* __restrict__ stats, int n) {
    constexpr int VEC = F / 32;  // 2 or 4
    __shared__ float ssum[F], ssq[F];
    if (threadIdx.x < F) { ssum[threadIdx.x] = 0.f; ssq[threadIdx.x] = 0.f; }
    __syncthreads();

    int node = (blockIdx.x * blockDim.x + threadIdx.x) >> 5;
    int lane = threadIdx.x & 31;
    float acc[VEC];
    #pragma unroll
    for (int v = 0; v < VEC; v++) acc[v] = 0.f;

    if (node < n) {
        int beg = offs[node], end = offs[node + 1];
        float dc = dinv[node];
        for (int i = beg; i < end; i += 32) {
            int idx = i + lane;
            int r = 0; float nd = 0.f;
            if (idx < end) { r = csr[idx]; nd = dinv[r]; }
            int cnt = min(32, end - i);
            int j = 0;
            for (; j + 4 <= cnt; j += 4) {
                unsigned r0 = (unsigned)__shfl_sync(0xffffffffu, r, j);
                unsigned r1 = (unsigned)__shfl_sync(0xffffffffu, r, j + 1);
                unsigned r2 = (unsigned)__shfl_sync(0xffffffffu, r, j + 2);
                unsigned r3 = (unsigned)__shfl_sync(0xffffffffu, r, j + 3);
                float n0 = __shfl_sync(0xffffffffu, nd, j) * dc;
                float n1 = __shfl_sync(0xffffffffu, nd, j + 1) * dc;
                float n2 = __shfl_sync(0xffffffffu, nd, j + 2) * dc;
                float n3 = __shfl_sync(0xffffffffu, nd, j + 3) * dc;
                if (VEC == 4) {
                    float4 v0 = ldh4(m + r0 * F + lane * 4);
                    float4 v1 = ldh4(m + r1 * F + lane * 4);
                    float4 v2 = ldh4(m + r2 * F + lane * 4);
                    float4 v3 = ldh4(m + r3 * F + lane * 4);
                    acc[0] = fmaf(n0, v0.x, fmaf(n1, v1.x, fmaf(n2, v2.x, fmaf(n3, v3.x, acc[0]))));
                    acc[1] = fmaf(n0, v0.y, fmaf(n1, v1.y, fmaf(n2, v2.y, fmaf(n3, v3.y, acc[1]))));
                    acc[2] = fmaf(n0, v0.z, fmaf(n1, v1.z, fmaf(n2, v2.z, fmaf(n3, v3.z, acc[2]))));
                    acc[3] = fmaf(n0, v0.w, fmaf(n1, v1.w, fmaf(n2, v2.w, fmaf(n3, v3.w, acc[3]))));
                } else {
                    float2 v0 = ldh2(m + r0 * F + lane * 2);
                    float2 v1 = ldh2(m + r1 * F + lane * 2);
                    float2 v2 = ldh2(m + r2 * F + lane * 2);
                    float2 v3 = ldh2(m + r3 * F + lane * 2);
                    acc[0] = fmaf(n0, v0.x, fmaf(n1, v1.x, fmaf(n2, v2.x, fmaf(n3, v3.x, acc[0]))));
                    acc[1] = fmaf(n0, v0.y, fmaf(n1, v1.y, fmaf(n2, v2.y, fmaf(n3, v3.y, acc[1]))));
                }
            }
            for (; j < cnt; j++) {
                unsigned rr = (unsigned)__shfl_sync(0xffffffffu, r, j);
                float nn = __shfl_sync(0xffffffffu, nd, j) * dc;
                if (VEC == 4) {
                    float4 v = ldh4(m + rr * F + lane * 4);
                    acc[0] = fmaf(nn, v.x, acc[0]);
                    acc[1] = fmaf(nn, v.y, acc[1]);
                    acc[2] = fmaf(nn, v.z, acc[2]);
                    acc[3] = fmaf(nn, v.w, acc[3]);
                } else {
                    float2 v = ldh2(m + rr * F + lane * 2);
                    acc[0] = fmaf(nn, v.x, acc[0]);
                    acc[1] = fmaf(nn, v.y, acc[1]);
                }
            }
        }
        if (VEC == 4)
            *(float4*)&agg[(unsigned)node * F + lane * 4] = make_float4(acc[0], acc[1], acc[2], acc[3]);
        else
            *(float2*)&agg[(unsigned)node * F + lane * 2] = make_float2(acc[0], acc[1]);
    }

    // fused BN statistics: block-reduce then one global atomic per channel
    #pragma unroll
    for (int v = 0; v < VEC; v++) {
        int c = lane * VEC + v;
        atomicAdd(&ssum[c], acc[v]);
        atomicAdd(&ssq[c], acc[v] * acc[v]);
    }
    __syncthreads();
    if (threadIdx.x < F) {
        atomicAdd(&stats[threadIdx.x], ssum[threadIdx.x]);
        atomicAdd(&stats[F + threadIdx.x], ssq[threadIdx.x]);
    }
}

// a = gamma * rsqrt(var+eps); shift = beta - a*mu  (GCN bias cancels in BN)
__global__ void finalize_kernel(const float* __restrict__ stats, const float* __restrict__ g,
                                const float* __restrict__ be, float* __restrict__ ab,
                                int n, int F) {
    int c = threadIdx.x;
    if (c < F) {
        float inv_n = 1.f / (float)n;
        float mu = stats[c] * inv_n;
        float var = fmaxf(stats[F + c] * inv_n - mu * mu, 0.f);
        float a = g[c] * rsqrtf(var + 1e-5f);
        ab[c] = a;
        ab[F + c] = be[c] - a * mu;
    }
}

// ---------------- FC1 with fused layer-1 epilogue on the A side ----------------
__global__ __launch_bounds__(256) void fc1_kernel(const float* __restrict__ agg0,
                                                  const float* __restrict__ proj0,
                                                  const float* __restrict__ ab_0,
                                                  const float* __restrict__ agg1,
                                                  const float* __restrict__ proj1,
                                                  const float* __restrict__ ab_1,
                                                  const float* __restrict__ B,
                                                  const float* __restrict__ bias,
                                                  float* __restrict__ H, int n) {
    __shared__ float As[64 * 64];
    __shared__ float Bs[64 * 128];
    int tid = threadIdx.x;
    int row0 = blockIdx.x * 64;
    int tm = tid >> 4, tn = tid & 15;
    float acc[4][8];
    #pragma unroll
    for (int i = 0; i < 4; i++)
        #pragma unroll
        for (int j = 0; j < 8; j++) acc[i][j] = 0.f;

    for (int c = 0; c < 4; c++) {
        __syncthreads();
        const float* agg = (c < 2) ? agg0 : agg1;
        const float* prj = (c < 2) ? proj0 : proj1;
        const float* ab  = (c < 2) ? ab_0 : ab_1;
        int kbase = (c & 1) * 64;
        #pragma unroll
        for (int i = 0; i < 16; i++) {
            int idx = tid + 256 * i;
            int r = idx >> 6, kk = idx & 63;
            float v = 0.f;
            if (row0 + r < n) {
                int ch = kbase + kk;
                unsigned o = (unsigned)(row0 + r) * 128u + ch;
                v = san(fmaf(ab[ch], agg[o], ab[128 + ch]) + prj[o]);
            }
            As[kk * 64 + r] = v;
        }
        #pragma unroll
        for (int i = 0; i < 32; i++) {
            int idx = tid + 256 * i;
            Bs[idx] = B[c * 64 * 128 + idx];
        }
        __syncthreads();
        #pragma unroll 4
        for (int k = 0; k < 64; k++) {
            float4 a = *(const float4*)&As[k * 64 + tm * 4];
            float b[8];
            *(float4*)&b[0] = *(const float4*)&Bs[k * 128 + tn * 8];
            *(float4*)&b[4] = *(const float4*)&Bs[k * 128 + tn * 8 + 4];
            float av[4] = {a.x, a.y, a.z, a.w};
            #pragma unroll
            for (int i = 0; i < 4; i++)
                #pragma unroll
                for (int j = 0; j < 8; j++) acc[i][j] = fmaf(av[i], b[j], acc[i][j]);
        }
    }
    #pragma unroll
    for (int i = 0; i < 4; i++) {
        int r = row0 + tm * 4 + i;
        if (r < n) {
            #pragma unroll
            for (int j = 0; j < 8; j++) {
                float v = acc[i][j] + bias[tn * 8 + j];
                H[(unsigned)r * 128 + tn * 8 + j] = fmaxf(v, 0.f);
            }
        }
    }
}

// ---------------- FC2 + softmax, one warp per node ----------------
__global__ void fc2_softmax_kernel(const float* __restrict__ H, const float* __restrict__ W2,
                                   const float* __restrict__ b2, float* __restrict__ out, int n) {
    int node = (blockIdx.x * blockDim.x + threadIdx.x) >> 5;
    int lane = threadIdx.x & 31;
    if (node >= n) return;
    float a0 = 0.f, a1 = 0.f;
    #pragma unroll
    for (int j = 0; j < 4; j++) {
        int k = lane + 32 * j;
        float h = H[(unsigned)node * 128 + k];
        a0 = fmaf(h, W2[k * 2 + 0], a0);
        a1 = fmaf(h, W2[k * 2 + 1], a1);
    }
    #pragma unroll
    for (int off = 16; off; off >>= 1) {
        a0 += __shfl_xor_sync(0xffffffffu, a0, off);
        a1 += __shfl_xor_sync(0xffffffffu, a1, off);
    }
    if (lane == 0) {
        float l0 = a0 + b2[0], l1 = a1 + b2[1];
        float mx = fmaxf(l0, l1);
        float e0 = expf(l0 - mx), e1 = expf(l1 - mx);
        float inv = 1.f / (e0 + e1);
        out[(size_t)node * 2 + 0] = l0;
        out[(size_t)node * 2 + 1] = l1;
        out[(size_t)2 * n + node * 2 + 0] = e0 * inv;
        out[(size_t)2 * n + node * 2 + 1] = e1 * inv;
    }
}

// ---------------- host launch (fork-join multi-stream, graph-capturable) ----------------
extern "C" void kernel_launch(void* const* d_in, const int* in_sizes, int n_in,
                              void* d_out, int out_size) {
    const float* x     = (const float*)d_in[0];
    const int*   ei[2] = {(const int*)d_in[1], (const int*)d_in[2]};
    const float* w0[2]   = {(const float*)d_in[3], (const float*)d_in[8]};
    const float* w1[2]   = {(const float*)d_in[5], (const float*)d_in[10]};
    const float* res1[2] = {(const float*)d_in[7], (const float*)d_in[12]};
    const float* bn_g0 = (const float*)d_in[13];
    const float* bn_b0 = (const float*)d_in[14];
    const float* bn_g1 = (const float*)d_in[15];
    const float* bn_b1 = (const float*)d_in[16];
    const float* fc1_w = (const float*)d_in[17];
    const float* fc1_b = (const float*)d_in[18];
    const float* fc2_w = (const float*)d_in[19];
    const float* fc2_b = (const float*)d_in[20];

    int n = in_sizes[0] / 64;
    int E = in_sizes[1] / 2;

    float *dinv_p[2], *agg0_p[2], *agg1_p[2], *proj_p[2];
    float *stats0_p[2], *stats1_p[2], *ab0_p[2], *ab1_p[2], *hfc_p;
    __half* m_p[2];
    int *deg_p[2], *offs_p[2], *cursor_p[2], *csr_p[2];
    {
        char* base;
        cudaGetSymbolAddress((void**)&base, g_dinv);
        dinv_p[0] = (float*)base; dinv_p[1] = dinv_p[0] + MAXN;
        cudaGetSymbolAddress((void**)&base, g_deg);
        deg_p[0] = (int*)base; deg_p[1] = deg_p[0] + MAXN;
        cudaGetSymbolAddress((void**)&base, g_offs);
        offs_p[0] = (int*)base; offs_p[1] = offs_p[0] + MAXNO;
        cudaGetSymbolAddress((void**)&base, g_cursor);
        cursor_p[0] = (int*)base; cursor_p[1] = cursor_p[0] + MAXN;
        cudaGetSymbolAddress((void**)&base, g_csr);
        csr_p[0] = (int*)base; csr_p[1] = csr_p[0] + MAXE;
        cudaGetSymbolAddress((void**)&base, g_m);
        m_p[0] = (__half*)base; m_p[1] = m_p[0] + (size_t)MAXN * 128;
        cudaGetSymbolAddress((void**)&base, g_agg0);
        agg0_p[0] = (float*)base; agg0_p[1] = agg0_p[0] + (size_t)MAXN * 64;
        cudaGetSymbolAddress((void**)&base, g_agg1);
        agg1_p[0] = (float*)base; agg1_p[1] = agg1_p[0] + (size_t)MAXN * 128;
        cudaGetSymbolAddress((void**)&base, g_proj);
        proj_p[0] = (float*)base; proj_p[1] = proj_p[0] + (size_t)MAXN * 128;
        cudaGetSymbolAddress((void**)&base, g_stats0);
        stats0_p[0] = (float*)base; stats0_p[1] = stats0_p[0] + 128;
        cudaGetSymbolAddress((void**)&base, g_stats1);
        stats1_p[0] = (float*)base; stats1_p[1] = stats1_p[0] + 256;
        cudaGetSymbolAddress((void**)&base, g_ab0);
        ab0_p[0] = (float*)base; ab0_p[1] = ab0_p[0] + 128;
        cudaGetSymbolAddress((void**)&base, g_ab1);
        ab1_p[0] = (float*)base; ab1_p[1] = ab1_p[0] + 256;
        cudaGetSymbolAddress((void**)&hfc_p, g_hfc);
    }

    int ebl = (E + 255) / 256;
    int gbl = (n + 63) / 64;   // gemm blocks (64 rows/block)
    int wbl = (n + 7) / 8;     // warp-per-node blocks (8 warps/block)

    cudaEventRecord(g_ev[0], 0);

    for (int s = 0; s < 2; s++) {
        const int* row = ei[s];
        const int* col = row + E;
        cudaStream_t a = g_str[2 * s];
        cudaStream_t b = g_str[2 * s + 1];
        cudaEvent_t evGemm0 = g_ev[1 + 4 * s];
        cudaEvent_t evFin0  = g_ev[2 + 4 * s];
        cudaEvent_t evProj  = g_ev[3 + 4 * s];
        cudaEvent_t evDone  = g_ev[4 + 4 * s];

        cudaStreamWaitEvent(a, g_ev[0], 0);
        cudaStreamWaitEvent(b, g_ev[0], 0);

        // stream b: stats zeroing + layer-0 transform GEMM (independent of CSR)
        cudaMemsetAsync(stats0_p[s], 0, 128 * sizeof(float), b);
        cudaMemsetAsync(stats1_p[s], 0, 256 * sizeof(float), b);
        sgemm64_kernel<64, false, true><<<gbl, 256, 0, b>>>(x, nullptr, nullptr, w0[s], m_p[s], n);
        cudaEventRecord(evGemm0, b);

        // stream a: CSR build chain
        cudaMemsetAsync(deg_p[s], 0, n * sizeof(int), a);
        deg_kernel<<<ebl, 256, 0, a>>>(col, deg_p[s], E);
        scan_kernel<<<1, 1024, 0, a>>>(deg_p[s], offs_p[s], cursor_p[s], dinv_p[s], n);
        csr_fill_kernel<<<ebl, 256, 0, a>>>(row, col, cursor_p[s], csr_p[s], E);

        // join: gather layer 0 (fused BN stats), finalize BN0
        cudaStreamWaitEvent(a, evGemm0, 0);
        gather_kernel<64><<<wbl, 256, 0, a>>>(csr_p[s], offs_p[s], dinv_p[s], m_p[s],
                                              agg0_p[s], stats0_p[s], n);
        finalize_kernel<<<1, 64, 0, a>>>(stats0_p[s], bn_g0, bn_b0, ab0_p[s], n, 64);
        cudaEventRecord(evFin0, a);

        // layer 1: m = h1' @ W1 (fp16 out) on a; proj = h1' @ res1 (fp32) on b
        sgemm64_kernel<128, true, true><<<gbl, 256, 0, a>>>(agg0_p[s], x, ab0_p[s], w1[s], m_p[s], n);
        cudaStreamWaitEvent(b, evFin0, 0);
        sgemm64_kernel<128, true, false><<<gbl, 256, 0, b>>>(agg0_p[s], x, ab0_p[s], res1[s], proj_p[s], n);
        cudaEventRecord(evProj, b);

        gather_kernel<128><<<wbl, 256, 0, a>>>(csr_p[s], offs_p[s], dinv_p[s], m_p[s],
                                               agg1_p[s], stats1_p[s], n);
        finalize_kernel<<<1, 128, 0, a>>>(stats1_p[s], bn_g1, bn_b1, ab1_p[s], n, 128);
        cudaStreamWaitEvent(a, evProj, 0);
        cudaEventRecord(evDone, a);
    }

    // join both slices back to origin stream; head
    cudaStreamWaitEvent(0, g_ev[4], 0);
    cudaStreamWaitEvent(0, g_ev[8], 0);
    fc1_kernel<<<gbl, 256>>>(agg1_p[0], proj_p[0], ab1_p[0],
                             agg1_p[1], proj_p[1], ab1_p[1],
                             fc1_w, fc1_b, hfc_p, n);
    fc2_softmax_kernel<<<wbl, 256>>>(hfc_p, fc2_w, fc2_b, (float*)d_out, n);
}

// round 7
// speedup vs baseline: 1.3108x; 1.0133x over previous
#include <cuda_runtime.h>
#include <cuda_bf16.h>
#include <cuda_fp16.h>
#include <math.h>

#define MAXN 50048           // divisible by 16
#define MAXNO (MAXN + 16)    // offs row stride, keeps slice-1 16B-aligned
#define MAXE 1600000

// ---------------- per-slice device scratch (static; no allocations) ----------------
__device__ __align__(16) float  g_dinv[2][MAXN];
__device__ __align__(16) int    g_deg[2][MAXN];
__device__ __align__(16) int    g_offs[2][MAXNO];
__device__ __align__(16) int    g_cursor[2][MAXN];
__device__ __align__(16) int    g_csr[2][MAXE];
__device__ __align__(16) __half g_m[2][(size_t)MAXN * 128];     // fp16, pre-scaled by dinv[row]
__device__ __align__(16) float  g_agg0[2][(size_t)MAXN * 64];
__device__ __align__(16) float  g_agg1[2][(size_t)MAXN * 128];
__device__ __align__(16) float  g_proj[2][(size_t)MAXN * 128];
__device__ __align__(16) float  g_stats0[2][128];
__device__ __align__(16) float  g_stats1[2][256];
__device__ __align__(16) float  g_ab0[2][128];
__device__ __align__(16) float  g_ab1[2][256];
__device__ __align__(16) float  g_hfc[(size_t)MAXN * 128];

// ---------------- static streams / events (host-side, created at load) ----------------
static cudaStream_t g_str[4];
static cudaEvent_t  g_ev[12];
static int g_init_streams = []() {
    for (int i = 0; i < 4; i++) cudaStreamCreateWithFlags(&g_str[i], cudaStreamNonBlocking);
    for (int i = 0; i < 12; i++) cudaEventCreateWithFlags(&g_ev[i], cudaEventDisableTiming);
    return 0;
}();

// nan_to_num(nan=0, posinf=100, neginf=-100)
__device__ __forceinline__ float san(float v) {
    if (isnan(v)) return 0.f;
    if (isinf(v)) return v > 0.f ? 100.f : -100.f;
    return v;
}

__device__ __forceinline__ float4 ldh4(const __half* p) {
    uint2 w = *(const uint2*)p;
    float2 a = __half22float2(*(__half2*)&w.x);
    float2 b = __half22float2(*(__half2*)&w.y);
    return make_float4(a.x, a.y, b.x, b.y);
}
__device__ __forceinline__ float2 ldh2(const __half* p) {
    return __half22float2(*(const __half2*)p);
}

// ---------------- degree ----------------
__global__ void deg_kernel(const int* __restrict__ col, int* __restrict__ deg, int E) {
    int e = blockIdx.x * blockDim.x + threadIdx.x;
    if (e < E) atomicAdd(&deg[col[e]], 1);
}

// single-block exclusive scan (x4 vectorized) -> offs/cursor + fused dinv = rsqrt(deg)
__global__ void scan_kernel(const int* __restrict__ deg, int* __restrict__ offs,
                            int* __restrict__ cursor, float* __restrict__ dinv, int n) {
    __shared__ int wsum[32];
    __shared__ int carry_s;
    int tid = threadIdx.x;
    int lane = tid & 31, wid = tid >> 5;
    if (tid == 0) carry_s = 0;
    __syncthreads();
    int nIter = (n + 4095) >> 12;
    for (int it = 0; it < nIter; it++) {
        int i0 = (it << 12) + tid * 4;
        int v0 = 0, v1 = 0, v2 = 0, v3 = 0;
        if (i0 + 3 < n) {
            int4 t = *(const int4*)(deg + i0);
            v0 = t.x; v1 = t.y; v2 = t.z; v3 = t.w;
        } else {
            if (i0 < n)     v0 = deg[i0];
            if (i0 + 1 < n) v1 = deg[i0 + 1];
            if (i0 + 2 < n) v2 = deg[i0 + 2];
            if (i0 + 3 < n) v3 = deg[i0 + 3];
        }
        int s = v0 + v1 + v2 + v3;
        int x = s;
        #pragma unroll
        for (int off = 1; off < 32; off <<= 1) {
            int y = __shfl_up_sync(0xffffffffu, x, off);
            if (lane >= off) x += y;
        }
        if (lane == 31) wsum[wid] = x;
        __syncthreads();
        if (wid == 0) {
            int w = wsum[lane];
            #pragma unroll
            for (int off = 1; off < 32; off <<= 1) {
                int y = __shfl_up_sync(0xffffffffu, w, off);
                if (lane >= off) w += y;
            }
            wsum[lane] = w;
        }
        __syncthreads();
        int pre = (wid > 0) ? wsum[wid - 1] : 0;
        int total = wsum[31];
        int e0 = carry_s + pre + x - s;
        int o1 = e0 + v0, o2 = o1 + v1, o3 = o2 + v2;
        if (i0 + 3 < n) {
            *(int4*)(offs + i0)   = make_int4(e0, o1, o2, o3);
            *(int4*)(cursor + i0) = make_int4(e0, o1, o2, o3);
            float4 dv = make_float4(v0 > 0 ? rsqrtf((float)v0) : 0.f,
                                    v1 > 0 ? rsqrtf((float)v1) : 0.f,
                                    v2 > 0 ? rsqrtf((float)v2) : 0.f,
                                    v3 > 0 ? rsqrtf((float)v3) : 0.f);
            *(float4*)(dinv + i0) = dv;
        } else {
            int oo[4] = {e0, o1, o2, o3};
            int vv[4] = {v0, v1, v2, v3};
            for (int j = 0; j < 4; j++) {
                if (i0 + j < n) {
                    offs[i0 + j] = oo[j];
                    cursor[i0 + j] = oo[j];
                    dinv[i0 + j] = vv[j] > 0 ? rsqrtf((float)vv[j]) : 0.f;
                }
            }
        }
        __syncthreads();
        if (tid == 0) carry_s += total;
        __syncthreads();
    }
    if (tid == 0) offs[n] = carry_s;
}

__global__ void csr_fill_kernel(const int* __restrict__ row, const int* __restrict__ col,
                                int* __restrict__ cursor, int* __restrict__ csr, int E) {
    int e = blockIdx.x * blockDim.x + threadIdx.x;
    if (e < E) {
        int pos = atomicAdd(&cursor[col[e]], 1);
        csr[pos] = row[e];
    }
}

// ---------------- register-tiled SGEMM: C[n,NOUT] = A'[n,64] @ B[64,NOUT] ----------------
// FUSE_H1: A'[r,k] = san(relu(ab[k]*agg[r,k] + ab[64+k]) + x[r,k]).
// OUT_HALF: C stored as fp16. SCALE_ROW: C row r multiplied by rs[r] at store.
template <int NOUT, bool FUSE_H1, bool OUT_HALF, bool SCALE_ROW>
__global__ __launch_bounds__(256) void sgemm64_kernel(const float* __restrict__ A,
                                                      const float* __restrict__ X,
                                                      const float* __restrict__ ab,
                                                      const float* __restrict__ B,
                                                      const float* __restrict__ rs,
                                                      void* __restrict__ C, int n) {
    constexpr int TNW = NOUT / 16;  // 4 or 8
    __shared__ float As[64 * 64];   // [k][row]
    __shared__ float Bs[64 * NOUT]; // [k][out]
    int tid = threadIdx.x;
    int row0 = blockIdx.x * 64;
    #pragma unroll
    for (int i = 0; i < 16; i++) {
        int idx = tid + 256 * i;
        int r = idx >> 6, k = idx & 63;
        float v = 0.f;
        if (row0 + r < n) {
            unsigned o = (unsigned)(row0 + r) * 64u + k;
            if (FUSE_H1) {
                float t = fmaf(ab[k], A[o], ab[64 + k]);
                v = san(fmaxf(t, 0.f) + X[o]);
            } else {
                v = A[o];
            }
        }
        As[k * 64 + r] = v;
    }
    #pragma unroll
    for (int i = 0; i < 64 * NOUT / 256; i++) {
        int idx = tid + 256 * i;
        Bs[idx] = B[idx];
    }
    __syncthreads();
    int tm = tid >> 4, tn = tid & 15;
    float acc[4][TNW];
    #pragma unroll
    for (int i = 0; i < 4; i++)
        #pragma unroll
        for (int j = 0; j < TNW; j++) acc[i][j] = 0.f;
    #pragma unroll 4
    for (int k = 0; k < 64; k++) {
        float4 a = *(const float4*)&As[k * 64 + tm * 4];
        float b[TNW];
        *(float4*)&b[0] = *(const float4*)&Bs[k * NOUT + tn * TNW];
        if (TNW == 8) *(float4*)&b[4] = *(const float4*)&Bs[k * NOUT + tn * TNW + 4];
        float av[4] = {a.x, a.y, a.z, a.w};
        #pragma unroll
        for (int i = 0; i < 4; i++)
            #pragma unroll
            for (int j = 0; j < TNW; j++) acc[i][j] = fmaf(av[i], b[j], acc[i][j]);
    }
    #pragma unroll
    for (int i = 0; i < 4; i++) {
        int r = row0 + tm * 4 + i;
        if (r < n) {
            float sc = SCALE_ROW ? rs[r] : 1.f;
            if (OUT_HALF) {
                __half* Ch = (__half*)C;
                #pragma unroll
                for (int j = 0; j < TNW; j += 4) {
                    __half2 p0 = __floats2half2_rn(acc[i][j] * sc, acc[i][j + 1] * sc);
                    __half2 p1 = __floats2half2_rn(acc[i][j + 2] * sc, acc[i][j + 3] * sc);
                    uint2 w;
                    w.x = *(unsigned*)&p0;
                    w.y = *(unsigned*)&p1;
                    *(uint2*)&Ch[(unsigned)r * NOUT + tn * TNW + j] = w;
                }
            } else {
                float* Cf = (float*)C;
                #pragma unroll
                for (int j = 0; j < TNW; j += 4)
                    *(float4*)&Cf[(unsigned)r * NOUT + tn * TNW + j] =
                        make_float4(acc[i][j] * sc, acc[i][j + 1] * sc,
                                    acc[i][j + 2] * sc, acc[i][j + 3] * sc);
            }
        }
    }
}

// ---------------- CSR gather-aggregate (fp16 pre-scaled source) + fused BN stats ----------------
// m rows are pre-scaled by dinv[row]; agg[node] = dinv[node] * sum_{row in N(node)} m[row]
template <int F>
__global__ __launch_bounds__(256) void gather_kernel(const int* __restrict__ csr,
                                                     const int* __restrict__ offs,
                                                     const float* __restrict__ dinv,
                                                     const __half* __restrict__ m,
                                                     float* __restrict__ agg,
                                                     float* __restrict__ stats, int n) {
    constexpr int VEC = F / 32;  // 2 or 4
    __shared__ float ssum[F], ssq[F];
    if (threadIdx.x < F) { ssum[threadIdx.x] = 0.f; ssq[threadIdx.x] = 0.f; }
    __syncthreads();

    int node = (blockIdx.x * blockDim.x + threadIdx.x) >> 5;
    int lane = threadIdx.x & 31;
    float acc[VEC];
    #pragma unroll
    for (int v = 0; v < VEC; v++) acc[v] = 0.f;
    float out[VEC];
    #pragma unroll
    for (int v = 0; v < VEC; v++) out[v] = 0.f;

    if (node < n) {
        int beg = offs[node], end = offs[node + 1];
        float dc = dinv[node];
        for (int i = beg; i < end; i += 32) {
            int idx = i + lane;
            int r = (idx < end) ? csr[idx] : 0;
            int cnt = min(32, end - i);
            int j = 0;
            // 8-deep unrolled body: 8 outstanding loads per lane, add-only math
            for (; j + 8 <= cnt; j += 8) {
                unsigned rr[8];
                #pragma unroll
                for (int t = 0; t < 8; t++)
                    rr[t] = (unsigned)__shfl_sync(0xffffffffu, r, j + t);
                if (VEC == 4) {
                    float4 v[8];
                    #pragma unroll
                    for (int t = 0; t < 8; t++) v[t] = ldh4(m + rr[t] * F + lane * 4);
                    #pragma unroll
                    for (int t = 0; t < 8; t++) {
                        acc[0] += v[t].x; acc[1] += v[t].y;
                        acc[2] += v[t].z; acc[3] += v[t].w;
                    }
                } else {
                    float2 v[8];
                    #pragma unroll
                    for (int t = 0; t < 8; t++) v[t] = ldh2(m + rr[t] * F + lane * 2);
                    #pragma unroll
                    for (int t = 0; t < 8; t++) {
                        acc[0] += v[t].x; acc[1] += v[t].y;
                    }
                }
            }
            for (; j < cnt; j++) {
                unsigned rr = (unsigned)__shfl_sync(0xffffffffu, r, j);
                if (VEC == 4) {
                    float4 v = ldh4(m + rr * F + lane * 4);
                    acc[0] += v.x; acc[1] += v.y; acc[2] += v.z; acc[3] += v.w;
                } else {
                    float2 v = ldh2(m + rr * F + lane * 2);
                    acc[0] += v.x; acc[1] += v.y;
                }
            }
        }
        #pragma unroll
        for (int v = 0; v < VEC; v++) out[v] = acc[v] * dc;
        if (VEC == 4)
            *(float4*)&agg[(unsigned)node * F + lane * 4] = make_float4(out[0], out[1], out[2], out[3]);
        else
            *(float2*)&agg[(unsigned)node * F + lane * 2] = make_float2(out[0], out[1]);
    }

    // fused BN statistics: block-reduce then one global atomic per channel
    #pragma unroll
    for (int v = 0; v < VEC; v++) {
        int c = lane * VEC + v;
        atomicAdd(&ssum[c], out[v]);
        atomicAdd(&ssq[c], out[v] * out[v]);
    }
    __syncthreads();
    if (threadIdx.x < F) {
        atomicAdd(&stats[threadIdx.x], ssum[threadIdx.x]);
        atomicAdd(&stats[F + threadIdx.x], ssq[threadIdx.x]);
    }
}

// a = gamma * rsqrt(var+eps); shift = beta - a*mu  (GCN bias cancels in BN)
__global__ void finalize_kernel(const float* __restrict__ stats, const float* __restrict__ g,
                                const float* __restrict__ be, float* __restrict__ ab,
                                int n, int F) {
    int c = threadIdx.x;
    if (c < F) {
        float inv_n = 1.f / (float)n;
        float mu = stats[c] * inv_n;
        float var = fmaxf(stats[F + c] * inv_n - mu * mu, 0.f);
        float a = g[c] * rsqrtf(var + 1e-5f);
        ab[c] = a;
        ab[F + c] = be[c] - a * mu;
    }
}

// ---------------- FC1 with fused layer-1 epilogue on the A side ----------------
__global__ __launch_bounds__(256) void fc1_kernel(const float* __restrict__ agg0,
                                                  const float* __restrict__ proj0,
                                                  const float* __restrict__ ab_0,
                                                  const float* __restrict__ agg1,
                                                  const float* __restrict__ proj1,
                                                  const float* __restrict__ ab_1,
                                                  const float* __restrict__ B,
                                                  const float* __restrict__ bias,
                                                  float* __restrict__ H, int n) {
    __shared__ float As[64 * 64];
    __shared__ float Bs[64 * 128];
    int tid = threadIdx.x;
    int row0 = blockIdx.x * 64;
    int tm = tid >> 4, tn = tid & 15;
    float acc[4][8];
    #pragma unroll
    for (int i = 0; i < 4; i++)
        #pragma unroll
        for (int j = 0; j < 8; j++) acc[i][j] = 0.f;

    for (int c = 0; c < 4; c++) {
        __syncthreads();
        const float* agg = (c < 2) ? agg0 : agg1;
        const float* prj = (c < 2) ? proj0 : proj1;
        const float* ab  = (c < 2) ? ab_0 : ab_1;
        int kbase = (c & 1) * 64;
        #pragma unroll
        for (int i = 0; i < 16; i++) {
            int idx = tid + 256 * i;
            int r = idx >> 6, kk = idx & 63;
            float v = 0.f;
            if (row0 + r < n) {
                int ch = kbase + kk;
                unsigned o = (unsigned)(row0 + r) * 128u + ch;
                v = san(fmaf(ab[ch], agg[o], ab[128 + ch]) + prj[o]);
            }
            As[kk * 64 + r] = v;
        }
        #pragma unroll
        for (int i = 0; i < 32; i++) {
            int idx = tid + 256 * i;
            Bs[idx] = B[c * 64 * 128 + idx];
        }
        __syncthreads();
        #pragma unroll 4
        for (int k = 0; k < 64; k++) {
            float4 a = *(const float4*)&As[k * 64 + tm * 4];
            float b[8];
            *(float4*)&b[0] = *(const float4*)&Bs[k * 128 + tn * 8];
            *(float4*)&b[4] = *(const float4*)&Bs[k * 128 + tn * 8 + 4];
            float av[4] = {a.x, a.y, a.z, a.w};
            #pragma unroll
            for (int i = 0; i < 4; i++)
                #pragma unroll
                for (int j = 0; j < 8; j++) acc[i][j] = fmaf(av[i], b[j], acc[i][j]);
        }
    }
    #pragma unroll
    for (int i = 0; i < 4; i++) {
        int r = row0 + tm * 4 + i;
        if (r < n) {
            #pragma unroll
            for (int j = 0; j < 8; j++) {
                float v = acc[i][j] + bias[tn * 8 + j];
                H[(unsigned)r * 128 + tn * 8 + j] = fmaxf(v, 0.f);
            }
        }
    }
}

// ---------------- FC2 + softmax, one warp per node ----------------
__global__ void fc2_softmax_kernel(const float* __restrict__ H, const float* __restrict__ W2,
                                   const float* __restrict__ b2, float* __restrict__ out, int n) {
    int node = (blockIdx.x * blockDim.x + threadIdx.x) >> 5;
    int lane = threadIdx.x & 31;
    if (node >= n) return;
    float a0 = 0.f, a1 = 0.f;
    #pragma unroll
    for (int j = 0; j < 4; j++) {
        int k = lane + 32 * j;
        float h = H[(unsigned)node * 128 + k];
        a0 = fmaf(h, W2[k * 2 + 0], a0);
        a1 = fmaf(h, W2[k * 2 + 1], a1);
    }
    #pragma unroll
    for (int off = 16; off; off >>= 1) {
        a0 += __shfl_xor_sync(0xffffffffu, a0, off);
        a1 += __shfl_xor_sync(0xffffffffu, a1, off);
    }
    if (lane == 0) {
        float l0 = a0 + b2[0], l1 = a1 + b2[1];
        float mx = fmaxf(l0, l1);
        float e0 = expf(l0 - mx), e1 = expf(l1 - mx);
        float inv = 1.f / (e0 + e1);
        out[(size_t)node * 2 + 0] = l0;
        out[(size_t)node * 2 + 1] = l1;
        out[(size_t)2 * n + node * 2 + 0] = e0 * inv;
        out[(size_t)2 * n + node * 2 + 1] = e1 * inv;
    }
}

// ---------------- host launch (fork-join multi-stream, graph-capturable) ----------------
extern "C" void kernel_launch(void* const* d_in, const int* in_sizes, int n_in,
                              void* d_out, int out_size) {
    const float* x     = (const float*)d_in[0];
    const int*   ei[2] = {(const int*)d_in[1], (const int*)d_in[2]};
    const float* w0[2]   = {(const float*)d_in[3], (const float*)d_in[8]};
    const float* w1[2]   = {(const float*)d_in[5], (const float*)d_in[10]};
    const float* res1[2] = {(const float*)d_in[7], (const float*)d_in[12]};
    const float* bn_g0 = (const float*)d_in[13];
    const float* bn_b0 = (const float*)d_in[14];
    const float* bn_g1 = (const float*)d_in[15];
    const float* bn_b1 = (const float*)d_in[16];
    const float* fc1_w = (const float*)d_in[17];
    const float* fc1_b = (const float*)d_in[18];
    const float* fc2_w = (const float*)d_in[19];
    const float* fc2_b = (const float*)d_in[20];

    int n = in_sizes[0] / 64;
    int E = in_sizes[1] / 2;

    float *dinv_p[2], *agg0_p[2], *agg1_p[2], *proj_p[2];
    float *stats0_p[2], *stats1_p[2], *ab0_p[2], *ab1_p[2], *hfc_p;
    __half* m_p[2];
    int *deg_p[2], *offs_p[2], *cursor_p[2], *csr_p[2];
    {
        char* base;
        cudaGetSymbolAddress((void**)&base, g_dinv);
        dinv_p[0] = (float*)base; dinv_p[1] = dinv_p[0] + MAXN;
        cudaGetSymbolAddress((void**)&base, g_deg);
        deg_p[0] = (int*)base; deg_p[1] = deg_p[0] + MAXN;
        cudaGetSymbolAddress((void**)&base, g_offs);
        offs_p[0] = (int*)base; offs_p[1] = offs_p[0] + MAXNO;
        cudaGetSymbolAddress((void**)&base, g_cursor);
        cursor_p[0] = (int*)base; cursor_p[1] = cursor_p[0] + MAXN;
        cudaGetSymbolAddress((void**)&base, g_csr);
        csr_p[0] = (int*)base; csr_p[1] = csr_p[0] + MAXE;
        cudaGetSymbolAddress((void**)&base, g_m);
        m_p[0] = (__half*)base; m_p[1] = m_p[0] + (size_t)MAXN * 128;
        cudaGetSymbolAddress((void**)&base, g_agg0);
        agg0_p[0] = (float*)base; agg0_p[1] = agg0_p[0] + (size_t)MAXN * 64;
        cudaGetSymbolAddress((void**)&base, g_agg1);
        agg1_p[0] = (float*)base; agg1_p[1] = agg1_p[0] + (size_t)MAXN * 128;
        cudaGetSymbolAddress((void**)&base, g_proj);
        proj_p[0] = (float*)base; proj_p[1] = proj_p[0] + (size_t)MAXN * 128;
        cudaGetSymbolAddress((void**)&base, g_stats0);
        stats0_p[0] = (float*)base; stats0_p[1] = stats0_p[0] + 128;
        cudaGetSymbolAddress((void**)&base, g_stats1);
        stats1_p[0] = (float*)base; stats1_p[1] = stats1_p[0] + 256;
        cudaGetSymbolAddress((void**)&base, g_ab0);
        ab0_p[0] = (float*)base; ab0_p[1] = ab0_p[0] + 128;
        cudaGetSymbolAddress((void**)&base, g_ab1);
        ab1_p[0] = (float*)base; ab1_p[1] = ab1_p[0] + 256;
        cudaGetSymbolAddress((void**)&hfc_p, g_hfc);
    }

    int ebl = (E + 255) / 256;
    int gbl = (n + 63) / 64;   // gemm blocks (64 rows/block)
    int wbl = (n + 7) / 8;     // warp-per-node blocks (8 warps/block)

    // events: 0 root; per slice s (stride 5): +1 scan, +2 fin0, +3 proj, +4 done
    cudaEventRecord(g_ev[0], 0);

    for (int s = 0; s < 2; s++) {
        const int* row = ei[s];
        const int* col = row + E;
        cudaStream_t a = g_str[2 * s];
        cudaStream_t b = g_str[2 * s + 1];
        cudaEvent_t evScan = g_ev[1 + 5 * s];
        cudaEvent_t evFin0 = g_ev[2 + 5 * s];
        cudaEvent_t evProj = g_ev[3 + 5 * s];
        cudaEvent_t evDone = g_ev[4 + 5 * s];

        cudaStreamWaitEvent(a, g_ev[0], 0);
        cudaStreamWaitEvent(b, g_ev[0], 0);

        // stream a: degree -> scan (dinv) -> csr_fill
        cudaMemsetAsync(deg_p[s], 0, n * sizeof(int), a);
        deg_kernel<<<ebl, 256, 0, a>>>(col, deg_p[s], E);
        scan_kernel<<<1, 1024, 0, a>>>(deg_p[s], offs_p[s], cursor_p[s], dinv_p[s], n);
        cudaEventRecord(evScan, a);
        csr_fill_kernel<<<ebl, 256, 0, a>>>(row, col, cursor_p[s], csr_p[s], E);

        // stream b: stats zeroing + layer-0 GEMM (row-scaled by dinv; waits on scan)
        cudaMemsetAsync(stats0_p[s], 0, 128 * sizeof(float), b);
        cudaMemsetAsync(stats1_p[s], 0, 256 * sizeof(float), b);
        cudaStreamWaitEvent(b, evScan, 0);
        sgemm64_kernel<64, false, true, true><<<gbl, 256, 0, b>>>(
            x, nullptr, nullptr, w0[s], dinv_p[s], m_p[s], n);
        cudaEventRecord(g_ev[5 + 5 * s], b);  // gemm0 done

        // join: gather layer 0 (fused BN stats), finalize BN0
        cudaStreamWaitEvent(a, g_ev[5 + 5 * s], 0);
        gather_kernel<64><<<wbl, 256, 0, a>>>(csr_p[s], offs_p[s], dinv_p[s], m_p[s],
                                              agg0_p[s], stats0_p[s], n);
        finalize_kernel<<<1, 64, 0, a>>>(stats0_p[s], bn_g0, bn_b0, ab0_p[s], n, 64);
        cudaEventRecord(evFin0, a);

        // layer 1: m = dinv*(h1' @ W1) (fp16) on a; proj = h1' @ res1 (fp32) on b
        sgemm64_kernel<128, true, true, true><<<gbl, 256, 0, a>>>(
            agg0_p[s], x, ab0_p[s], w1[s], dinv_p[s], m_p[s], n);
        cudaStreamWaitEvent(b, evFin0, 0);
        sgemm64_kernel<128, true, false, false><<<gbl, 256, 0, b>>>(
            agg0_p[s], x, ab0_p[s], res1[s], nullptr, proj_p[s], n);
        cudaEventRecord(evProj, b);

        gather_kernel<128><<<wbl, 256, 0, a>>>(csr_p[s], offs_p[s], dinv_p[s], m_p[s],
                                               agg1_p[s], stats1_p[s], n);
        finalize_kernel<<<1, 128, 0, a>>>(stats1_p[s], bn_g1, bn_b1, ab1_p[s], n, 128);
        cudaStreamWaitEvent(a, evProj, 0);
        cudaEventRecord(evDone, a);
    }

    // join both slices back to origin stream; head
    cudaStreamWaitEvent(0, g_ev[4], 0);
    cudaStreamWaitEvent(0, g_ev[9], 0);
    fc1_kernel<<<gbl, 256>>>(agg1_p[0], proj_p[0], ab1_p[0],
                             agg1_p[1], proj_p[1], ab1_p[1],
                             fc1_w, fc1_b, hfc_p, n);
    fc2_softmax_kernel<<<wbl, 256>>>(hfc_p, fc2_w, fc2_b, (float*)d_out, n);
}

// round 8
// speedup vs baseline: 2.2027x; 1.6805x over previous
#include <cuda_runtime.h>
#include <cuda_bf16.h>
#include <cuda_fp16.h>
#include <math.h>

#define MAXN 50048           // divisible by 16
#define MAXNO (MAXN + 16)    // offs row stride, keeps slice-1 16B-aligned
#define MAXE 1600000

// ---------------- per-slice device scratch (static; no allocations) ----------------
__device__ __align__(16) float  g_dinv[2][MAXN];
__device__ __align__(16) int    g_deg[2][MAXN];
__device__ __align__(16) int    g_offs[2][MAXNO];
__device__ __align__(16) int    g_cursor[2][MAXN];
__device__ __align__(16) int    g_csr[2][MAXE];
__device__ __align__(16) __half g_m[2][(size_t)MAXN * 128];     // fp16, pre-scaled by dinv[row]
__device__ __align__(16) float  g_agg0[2][(size_t)MAXN * 64];
__device__ __align__(16) float  g_agg1[2][(size_t)MAXN * 128];
__device__ __align__(16) float  g_proj[2][(size_t)MAXN * 128];
__device__ __align__(16) float  g_stats0[2][128];
__device__ __align__(16) float  g_stats1[2][256];
__device__ __align__(16) float  g_ab0[2][128];
__device__ __align__(16) float  g_ab1[2][256];
__device__ __align__(16) float  g_hfc[(size_t)MAXN * 128];

// ---------------- static streams / events (host-side, created at load) ----------------
static cudaStream_t g_str[4];
static cudaEvent_t  g_ev[12];
static int g_init_streams = []() {
    for (int i = 0; i < 4; i++) cudaStreamCreateWithFlags(&g_str[i], cudaStreamNonBlocking);
    for (int i = 0; i < 12; i++) cudaEventCreateWithFlags(&g_ev[i], cudaEventDisableTiming);
    return 0;
}();

// nan_to_num(nan=0, posinf=100, neginf=-100)
__device__ __forceinline__ float san(float v) {
    if (isnan(v)) return 0.f;
    if (isinf(v)) return v > 0.f ? 100.f : -100.f;
    return v;
}

__device__ __forceinline__ unsigned h2u(__half2 h) { return *(unsigned*)&h; }

__device__ __forceinline__ float4 ldh4(const __half* p) {
    uint2 w = *(const uint2*)p;
    float2 a = __half22float2(*(__half2*)&w.x);
    float2 b = __half22float2(*(__half2*)&w.y);
    return make_float4(a.x, a.y, b.x, b.y);
}
__device__ __forceinline__ float2 ldh2(const __half* p) {
    return __half22float2(*(const __half2*)p);
}

// m16n8k16 f16xf16 -> f32 accumulate
__device__ __forceinline__ void mma16816(float* c, const unsigned* a, unsigned b0, unsigned b1) {
    asm volatile(
        "mma.sync.aligned.m16n8k16.row.col.f32.f16.f16.f32 "
        "{%0,%1,%2,%3}, {%4,%5,%6,%7}, {%8,%9}, {%0,%1,%2,%3};"
        : "+f"(c[0]), "+f"(c[1]), "+f"(c[2]), "+f"(c[3])
        : "r"(a[0]), "r"(a[1]), "r"(a[2]), "r"(a[3]), "r"(b0), "r"(b1));
}

// ---------------- degree ----------------
__global__ void deg_kernel(const int* __restrict__ col, int* __restrict__ deg, int E) {
    int e = blockIdx.x * blockDim.x + threadIdx.x;
    if (e < E) atomicAdd(&deg[col[e]], 1);
}

// single-block exclusive scan (x4 vectorized) -> offs/cursor + fused dinv = rsqrt(deg)
__global__ void scan_kernel(const int* __restrict__ deg, int* __restrict__ offs,
                            int* __restrict__ cursor, float* __restrict__ dinv, int n) {
    __shared__ int wsum[32];
    __shared__ int carry_s;
    int tid = threadIdx.x;
    int lane = tid & 31, wid = tid >> 5;
    if (tid == 0) carry_s = 0;
    __syncthreads();
    int nIter = (n + 4095) >> 12;
    for (int it = 0; it < nIter; it++) {
        int i0 = (it << 12) + tid * 4;
        int v0 = 0, v1 = 0, v2 = 0, v3 = 0;
        if (i0 + 3 < n) {
            int4 t = *(const int4*)(deg + i0);
            v0 = t.x; v1 = t.y; v2 = t.z; v3 = t.w;
        } else {
            if (i0 < n)     v0 = deg[i0];
            if (i0 + 1 < n) v1 = deg[i0 + 1];
            if (i0 + 2 < n) v2 = deg[i0 + 2];
            if (i0 + 3 < n) v3 = deg[i0 + 3];
        }
        int s = v0 + v1 + v2 + v3;
        int x = s;
        #pragma unroll
        for (int off = 1; off < 32; off <<= 1) {
            int y = __shfl_up_sync(0xffffffffu, x, off);
            if (lane >= off) x += y;
        }
        if (lane == 31) wsum[wid] = x;
        __syncthreads();
        if (wid == 0) {
            int w = wsum[lane];
            #pragma unroll
            for (int off = 1; off < 32; off <<= 1) {
                int y = __shfl_up_sync(0xffffffffu, w, off);
                if (lane >= off) w += y;
            }
            wsum[lane] = w;
        }
        __syncthreads();
        int pre = (wid > 0) ? wsum[wid - 1] : 0;
        int total = wsum[31];
        int e0 = carry_s + pre + x - s;
        int o1 = e0 + v0, o2 = o1 + v1, o3 = o2 + v2;
        if (i0 + 3 < n) {
            *(int4*)(offs + i0)   = make_int4(e0, o1, o2, o3);
            *(int4*)(cursor + i0) = make_int4(e0, o1, o2, o3);
            float4 dv = make_float4(v0 > 0 ? rsqrtf((float)v0) : 0.f,
                                    v1 > 0 ? rsqrtf((float)v1) : 0.f,
                                    v2 > 0 ? rsqrtf((float)v2) : 0.f,
                                    v3 > 0 ? rsqrtf((float)v3) : 0.f);
            *(float4*)(dinv + i0) = dv;
        } else {
            int oo[4] = {e0, o1, o2, o3};
            int vv[4] = {v0, v1, v2, v3};
            for (int j = 0; j < 4; j++) {
                if (i0 + j < n) {
                    offs[i0 + j] = oo[j];
                    cursor[i0 + j] = oo[j];
                    dinv[i0 + j] = vv[j] > 0 ? rsqrtf((float)vv[j]) : 0.f;
                }
            }
        }
        __syncthreads();
        if (tid == 0) carry_s += total;
        __syncthreads();
    }
    if (tid == 0) offs[n] = carry_s;
}

__global__ void csr_fill_kernel(const int* __restrict__ row, const int* __restrict__ col,
                                int* __restrict__ cursor, int* __restrict__ csr, int E) {
    int e = blockIdx.x * blockDim.x + threadIdx.x;
    if (e < E) {
        int pos = atomicAdd(&cursor[col[e]], 1);
        csr[pos] = row[e];
    }
}

// ================= HMMA GEMM: C[n,NOUT] = A'[n,64] @ B[64,NOUT] =================
// PRO: 0 = raw A; 1 = h1 epilogue: san(relu(ab[k]*A+ab[64+k]) + X)
// STO: 0 = fp16 * rs[row]; 1 = fp32
// Block: 128 rows x NOUT cols, 256 threads (8 warps, 4x2 warp grid).
template <int NOUT, int PRO, int STO>
__global__ __launch_bounds__(256) void hgemm_kernel(const float* __restrict__ A,
                                                    const float* __restrict__ X,
                                                    const float* __restrict__ ab,
                                                    const float* __restrict__ B,
                                                    const float* __restrict__ rs,
                                                    void* __restrict__ C, int n) {
    constexpr int ASTR = 72;          // halves per A row (pad: 36 words -> 4-bank row shift)
    constexpr int BSTR = NOUT + 8;    // words per k-pair  (stride ≡ 8 mod 32)
    __shared__ __half  As[128 * ASTR];
    __shared__ unsigned Bs[32 * BSTR];

    int tid = threadIdx.x;
    int row0 = blockIdx.x * 128;

    // stage A: 128x64 fp32 -> fp16 (fused prologue); word = (row, kpair)
    #pragma unroll
    for (int i = 0; i < 16; i++) {
        int idx = tid + 256 * i;
        int r = idx >> 5, kp = idx & 31;
        float v0 = 0.f, v1 = 0.f;
        if (row0 + r < n) {
            unsigned o = (unsigned)(row0 + r) * 64u + kp * 2;
            if (PRO == 1) {
                float2 av = *(const float2*)&A[o];
                float2 xv = *(const float2*)&X[o];
                float t0 = fmaf(ab[kp * 2], av.x, ab[64 + kp * 2]);
                float t1 = fmaf(ab[kp * 2 + 1], av.y, ab[64 + kp * 2 + 1]);
                v0 = san(fmaxf(t0, 0.f) + xv.x);
                v1 = san(fmaxf(t1, 0.f) + xv.y);
            } else {
                float2 av = *(const float2*)&A[o];
                v0 = av.x; v1 = av.y;
            }
        }
        *(unsigned*)&As[r * ASTR + kp * 2] = h2u(__floats2half2_rn(v0, v1));
    }
    // stage B: word (kp, nn) = {B[2kp][nn], B[2kp+1][nn]} fp16x2
    constexpr int BW = (32 * NOUT) / 256;
    #pragma unroll
    for (int i = 0; i < BW; i++) {
        int idx = tid + 256 * i;
        int kp = idx / NOUT, nn = idx % NOUT;
        Bs[kp * BSTR + nn] = h2u(__floats2half2_rn(B[(2 * kp) * NOUT + nn],
                                                   B[(2 * kp + 1) * NOUT + nn]));
    }
    __syncthreads();

    int warp = tid >> 5, lane = tid & 31;
    constexpr int NT = NOUT / 16;     // n-tiles per warp (warp covers NOUT/2 cols)
    int wr = warp >> 1, wc = warp & 1;
    int rbase = wr * 32, nbase = wc * (NOUT / 2);
    int g = lane >> 2, q = lane & 3;

    float acc[2][NT][4];
    #pragma unroll
    for (int mt = 0; mt < 2; mt++)
        #pragma unroll
        for (int nt = 0; nt < NT; nt++)
            #pragma unroll
            for (int e = 0; e < 4; e++) acc[mt][nt][e] = 0.f;

    #pragma unroll
    for (int kk = 0; kk < 4; kk++) {
        unsigned a[2][4];
        #pragma unroll
        for (int mt = 0; mt < 2; mt++) {
            const __half* ap = &As[(rbase + mt * 16 + g) * ASTR + kk * 16 + q * 2];
            a[mt][0] = *(const unsigned*)ap;
            a[mt][1] = *(const unsigned*)(ap + 8 * ASTR);
            a[mt][2] = *(const unsigned*)(ap + 8);
            a[mt][3] = *(const unsigned*)(ap + 8 * ASTR + 8);
        }
        int kp = kk * 8 + q;
        #pragma unroll
        for (int nt = 0; nt < NT; nt++) {
            int nn = nbase + nt * 8 + g;
            unsigned b0 = Bs[kp * BSTR + nn];
            unsigned b1 = Bs[(kp + 4) * BSTR + nn];
            mma16816(acc[0][nt], a[0], b0, b1);
            mma16816(acc[1][nt], a[1], b0, b1);
        }
    }

    // store: c0,c1 -> row g, cols q*2, q*2+1; c2,c3 -> row g+8
    #pragma unroll
    for (int mt = 0; mt < 2; mt++) {
        #pragma unroll
        for (int h = 0; h < 2; h++) {
            int r = row0 + rbase + mt * 16 + g + h * 8;
            if (r < n) {
                float sc = (STO == 0) ? rs[r] : 1.f;
                #pragma unroll
                for (int nt = 0; nt < NT; nt++) {
                    float c0 = acc[mt][nt][h * 2], c1 = acc[mt][nt][h * 2 + 1];
                    int col = nbase + nt * 8 + q * 2;
                    if (STO == 0) {
                        *(unsigned*)&((__half*)C)[(unsigned)r * NOUT + col] =
                            h2u(__floats2half2_rn(c0 * sc, c1 * sc));
                    } else {
                        *(float2*)&((float*)C)[(unsigned)r * NOUT + col] = make_float2(c0, c1);
                    }
                }
            }
        }
    }
}

// ================= FC1 (HMMA): H = relu(concat(out0,out1)[n,256] @ W[256,128] + b) ======
// A chunk c (0..3): slice s=c>>1, kbase=(c&1)*64; A'[r,k] = san(ab[ch]*agg+ab[128+ch]+proj)
__global__ __launch_bounds__(256) void hfc1_kernel(const float* __restrict__ agg0,
                                                   const float* __restrict__ proj0,
                                                   const float* __restrict__ ab_0,
                                                   const float* __restrict__ agg1,
                                                   const float* __restrict__ proj1,
                                                   const float* __restrict__ ab_1,
                                                   const float* __restrict__ B,
                                                   const float* __restrict__ bias,
                                                   float* __restrict__ H, int n) {
    constexpr int ASTR = 72;
    constexpr int BSTR = 136;
    __shared__ __half  As[128 * ASTR];
    __shared__ unsigned Bs[32 * BSTR];

    int tid = threadIdx.x;
    int row0 = blockIdx.x * 128;
    int warp = tid >> 5, lane = tid & 31;
    int wr = warp >> 1, wc = warp & 1;
    int rbase = wr * 32, nbase = wc * 64;
    int g = lane >> 2, q = lane & 3;

    float acc[2][8][4];
    #pragma unroll
    for (int mt = 0; mt < 2; mt++)
        #pragma unroll
        for (int nt = 0; nt < 8; nt++)
            #pragma unroll
            for (int e = 0; e < 4; e++) acc[mt][nt][e] = 0.f;

    for (int c = 0; c < 4; c++) {
        __syncthreads();
        const float* agg = (c < 2) ? agg0 : agg1;
        const float* prj = (c < 2) ? proj0 : proj1;
        const float* ab  = (c < 2) ? ab_0 : ab_1;
        int kbase = (c & 1) * 64;
        #pragma unroll
        for (int i = 0; i < 16; i++) {
            int idx = tid + 256 * i;
            int r = idx >> 5, kp = idx & 31;
            float v0 = 0.f, v1 = 0.f;
            if (row0 + r < n) {
                int ch = kbase + kp * 2;
                unsigned o = (unsigned)(row0 + r) * 128u + ch;
                float2 av = *(const float2*)&agg[o];
                float2 pv = *(const float2*)&prj[o];
                v0 = san(fmaf(ab[ch], av.x, ab[128 + ch]) + pv.x);
                v1 = san(fmaf(ab[ch + 1], av.y, ab[128 + ch + 1]) + pv.y);
            }
            *(unsigned*)&As[r * ASTR + kp * 2] = h2u(__floats2half2_rn(v0, v1));
        }
        const float* Bc = B + c * 64 * 128;
        #pragma unroll
        for (int i = 0; i < 16; i++) {
            int idx = tid + 256 * i;
            int kp = idx >> 7, nn = idx & 127;
            Bs[kp * BSTR + nn] = h2u(__floats2half2_rn(Bc[(2 * kp) * 128 + nn],
                                                       Bc[(2 * kp + 1) * 128 + nn]));
        }
        __syncthreads();

        #pragma unroll
        for (int kk = 0; kk < 4; kk++) {
            unsigned a[2][4];
            #pragma unroll
            for (int mt = 0; mt < 2; mt++) {
                const __half* ap = &As[(rbase + mt * 16 + g) * ASTR + kk * 16 + q * 2];
                a[mt][0] = *(const unsigned*)ap;
                a[mt][1] = *(const unsigned*)(ap + 8 * ASTR);
                a[mt][2] = *(const unsigned*)(ap + 8);
                a[mt][3] = *(const unsigned*)(ap + 8 * ASTR + 8);
            }
            int kp = kk * 8 + q;
            #pragma unroll
            for (int nt = 0; nt < 8; nt++) {
                int nn = nbase + nt * 8 + g;
                unsigned b0 = Bs[kp * BSTR + nn];
                unsigned b1 = Bs[(kp + 4) * BSTR + nn];
                mma16816(acc[0][nt], a[0], b0, b1);
                mma16816(acc[1][nt], a[1], b0, b1);
            }
        }
    }

    #pragma unroll
    for (int mt = 0; mt < 2; mt++) {
        #pragma unroll
        for (int h = 0; h < 2; h++) {
            int r = row0 + rbase + mt * 16 + g + h * 8;
            if (r < n) {
                #pragma unroll
                for (int nt = 0; nt < 8; nt++) {
                    int col = nbase + nt * 8 + q * 2;
                    float c0 = fmaxf(acc[mt][nt][h * 2] + bias[col], 0.f);
                    float c1 = fmaxf(acc[mt][nt][h * 2 + 1] + bias[col + 1], 0.f);
                    *(float2*)&H[(unsigned)r * 128 + col] = make_float2(c0, c1);
                }
            }
        }
    }
}

// ---------------- CSR gather-aggregate (fp16 pre-scaled source) + fused BN stats ----------------
template <int F>
__global__ __launch_bounds__(256) void gather_kernel(const int* __restrict__ csr,
                                                     const int* __restrict__ offs,
                                                     const float* __restrict__ dinv,
                                                     const __half* __restrict__ m,
                                                     float* __restrict__ agg,
                                                     float* __restrict__ stats, int n) {
    constexpr int VEC = F / 32;  // 2 or 4
    __shared__ float ssum[F], ssq[F];
    if (threadIdx.x < F) { ssum[threadIdx.x] = 0.f; ssq[threadIdx.x] = 0.f; }
    __syncthreads();

    int node = (blockIdx.x * blockDim.x + threadIdx.x) >> 5;
    int lane = threadIdx.x & 31;
    float acc[VEC];
    #pragma unroll
    for (int v = 0; v < VEC; v++) acc[v] = 0.f;
    float out[VEC];
    #pragma unroll
    for (int v = 0; v < VEC; v++) out[v] = 0.f;

    if (node < n) {
        int beg = offs[node], end = offs[node + 1];
        float dc = dinv[node];
        for (int i = beg; i < end; i += 32) {
            int idx = i + lane;
            int r = (idx < end) ? csr[idx] : 0;
            int cnt = min(32, end - i);
            int j = 0;
            for (; j + 8 <= cnt; j += 8) {
                unsigned rr[8];
                #pragma unroll
                for (int t = 0; t < 8; t++)
                    rr[t] = (unsigned)__shfl_sync(0xffffffffu, r, j + t);
                if (VEC == 4) {
                    float4 v[8];
                    #pragma unroll
                    for (int t = 0; t < 8; t++) v[t] = ldh4(m + rr[t] * F + lane * 4);
                    #pragma unroll
                    for (int t = 0; t < 8; t++) {
                        acc[0] += v[t].x; acc[1] += v[t].y;
                        acc[2] += v[t].z; acc[3] += v[t].w;
                    }
                } else {
                    float2 v[8];
                    #pragma unroll
                    for (int t = 0; t < 8; t++) v[t] = ldh2(m + rr[t] * F + lane * 2);
                    #pragma unroll
                    for (int t = 0; t < 8; t++) {
                        acc[0] += v[t].x; acc[1] += v[t].y;
                    }
                }
            }
            for (; j < cnt; j++) {
                unsigned rr = (unsigned)__shfl_sync(0xffffffffu, r, j);
                if (VEC == 4) {
                    float4 v = ldh4(m + rr * F + lane * 4);
                    acc[0] += v.x; acc[1] += v.y; acc[2] += v.z; acc[3] += v.w;
                } else {
                    float2 v = ldh2(m + rr * F + lane * 2);
                    acc[0] += v.x; acc[1] += v.y;
                }
            }
        }
        #pragma unroll
        for (int v = 0; v < VEC; v++) out[v] = acc[v] * dc;
        if (VEC == 4)
            *(float4*)&agg[(unsigned)node * F + lane * 4] = make_float4(out[0], out[1], out[2], out[3]);
        else
            *(float2*)&agg[(unsigned)node * F + lane * 2] = make_float2(out[0], out[1]);
    }

    #pragma unroll
    for (int v = 0; v < VEC; v++) {
        int c = lane * VEC + v;
        atomicAdd(&ssum[c], out[v]);
        atomicAdd(&ssq[c], out[v] * out[v]);
    }
    __syncthreads();
    if (threadIdx.x < F) {
        atomicAdd(&stats[threadIdx.x], ssum[threadIdx.x]);
        atomicAdd(&stats[F + threadIdx.x], ssq[threadIdx.x]);
    }
}

// a = gamma * rsqrt(var+eps); shift = beta - a*mu  (GCN bias cancels in BN)
__global__ void finalize_kernel(const float* __restrict__ stats, const float* __restrict__ g,
                                const float* __restrict__ be, float* __restrict__ ab,
                                int n, int F) {
    int c = threadIdx.x;
    if (c < F) {
        float inv_n = 1.f / (float)n;
        float mu = stats[c] * inv_n;
        float var = fmaxf(stats[F + c] * inv_n - mu * mu, 0.f);
        float a = g[c] * rsqrtf(var + 1e-5f);
        ab[c] = a;
        ab[F + c] = be[c] - a * mu;
    }
}

// ---------------- FC2 + softmax, one warp per node ----------------
__global__ void fc2_softmax_kernel(const float* __restrict__ H, const float* __restrict__ W2,
                                   const float* __restrict__ b2, float* __restrict__ out, int n) {
    int node = (blockIdx.x * blockDim.x + threadIdx.x) >> 5;
    int lane = threadIdx.x & 31;
    if (node >= n) return;
    float a0 = 0.f, a1 = 0.f;
    #pragma unroll
    for (int j = 0; j < 4; j++) {
        int k = lane + 32 * j;
        float h = H[(unsigned)node * 128 + k];
        a0 = fmaf(h, W2[k * 2 + 0], a0);
        a1 = fmaf(h, W2[k * 2 + 1], a1);
    }
    #pragma unroll
    for (int off = 16; off; off >>= 1) {
        a0 += __shfl_xor_sync(0xffffffffu, a0, off);
        a1 += __shfl_xor_sync(0xffffffffu, a1, off);
    }
    if (lane == 0) {
        float l0 = a0 + b2[0], l1 = a1 + b2[1];
        float mx = fmaxf(l0, l1);
        float e0 = expf(l0 - mx), e1 = expf(l1 - mx);
        float inv = 1.f / (e0 + e1);
        out[(size_t)node * 2 + 0] = l0;
        out[(size_t)node * 2 + 1] = l1;
        out[(size_t)2 * n + node * 2 + 0] = e0 * inv;
        out[(size_t)2 * n + node * 2 + 1] = e1 * inv;
    }
}

// ---------------- host launch (fork-join multi-stream, graph-capturable) ----------------
extern "C" void kernel_launch(void* const* d_in, const int* in_sizes, int n_in,
                              void* d_out, int out_size) {
    const float* x     = (const float*)d_in[0];
    const int*   ei[2] = {(const int*)d_in[1], (const int*)d_in[2]};
    const float* w0[2]   = {(const float*)d_in[3], (const float*)d_in[8]};
    const float* w1[2]   = {(const float*)d_in[5], (const float*)d_in[10]};
    const float* res1[2] = {(const float*)d_in[7], (const float*)d_in[12]};
    const float* bn_g0 = (const float*)d_in[13];
    const float* bn_b0 = (const float*)d_in[14];
    const float* bn_g1 = (const float*)d_in[15];
    const float* bn_b1 = (const float*)d_in[16];
    const float* fc1_w = (const float*)d_in[17];
    const float* fc1_b = (const float*)d_in[18];
    const float* fc2_w = (const float*)d_in[19];
    const float* fc2_b = (const float*)d_in[20];

    int n = in_sizes[0] / 64;
    int E = in_sizes[1] / 2;

    float *dinv_p[2], *agg0_p[2], *agg1_p[2], *proj_p[2];
    float *stats0_p[2], *stats1_p[2], *ab0_p[2], *ab1_p[2], *hfc_p;
    __half* m_p[2];
    int *deg_p[2], *offs_p[2], *cursor_p[2], *csr_p[2];
    {
        char* base;
        cudaGetSymbolAddress((void**)&base, g_dinv);
        dinv_p[0] = (float*)base; dinv_p[1] = dinv_p[0] + MAXN;
        cudaGetSymbolAddress((void**)&base, g_deg);
        deg_p[0] = (int*)base; deg_p[1] = deg_p[0] + MAXN;
        cudaGetSymbolAddress((void**)&base, g_offs);
        offs_p[0] = (int*)base; offs_p[1] = offs_p[0] + MAXNO;
        cudaGetSymbolAddress((void**)&base, g_cursor);
        cursor_p[0] = (int*)base; cursor_p[1] = cursor_p[0] + MAXN;
        cudaGetSymbolAddress((void**)&base, g_csr);
        csr_p[0] = (int*)base; csr_p[1] = csr_p[0] + MAXE;
        cudaGetSymbolAddress((void**)&base, g_m);
        m_p[0] = (__half*)base; m_p[1] = m_p[0] + (size_t)MAXN * 128;
        cudaGetSymbolAddress((void**)&base, g_agg0);
        agg0_p[0] = (float*)base; agg0_p[1] = agg0_p[0] + (size_t)MAXN * 64;
        cudaGetSymbolAddress((void**)&base, g_agg1);
        agg1_p[0] = (float*)base; agg1_p[1] = agg1_p[0] + (size_t)MAXN * 128;
        cudaGetSymbolAddress((void**)&base, g_proj);
        proj_p[0] = (float*)base; proj_p[1] = proj_p[0] + (size_t)MAXN * 128;
        cudaGetSymbolAddress((void**)&base, g_stats0);
        stats0_p[0] = (float*)base; stats0_p[1] = stats0_p[0] + 128;
        cudaGetSymbolAddress((void**)&base, g_stats1);
        stats1_p[0] = (float*)base; stats1_p[1] = stats1_p[0] + 256;
        cudaGetSymbolAddress((void**)&base, g_ab0);
        ab0_p[0] = (float*)base; ab0_p[1] = ab0_p[0] + 128;
        cudaGetSymbolAddress((void**)&base, g_ab1);
        ab1_p[0] = (float*)base; ab1_p[1] = ab1_p[0] + 256;
        cudaGetSymbolAddress((void**)&hfc_p, g_hfc);
    }

    int ebl = (E + 255) / 256;
    int hbl = (n + 127) / 128;  // hmma gemm blocks (128 rows/block)
    int wbl = (n + 7) / 8;      // warp-per-node blocks (8 warps/block)

    // events: 0 root; per slice s (stride 5): +1 scan, +2 fin0, +3 proj, +4 done, +5 gemm0
    cudaEventRecord(g_ev[0], 0);

    for (int s = 0; s < 2; s++) {
        const int* row = ei[s];
        const int* col = row + E;
        cudaStream_t a = g_str[2 * s];
        cudaStream_t b = g_str[2 * s + 1];
        cudaEvent_t evScan = g_ev[1 + 5 * s];
        cudaEvent_t evFin0 = g_ev[2 + 5 * s];
        cudaEvent_t evProj = g_ev[3 + 5 * s];
        cudaEvent_t evDone = g_ev[4 + 5 * s];

        cudaStreamWaitEvent(a, g_ev[0], 0);
        cudaStreamWaitEvent(b, g_ev[0], 0);

        // stream a: degree -> scan (dinv) -> csr_fill
        cudaMemsetAsync(deg_p[s], 0, n * sizeof(int), a);
        deg_kernel<<<ebl, 256, 0, a>>>(col, deg_p[s], E);
        scan_kernel<<<1, 1024, 0, a>>>(deg_p[s], offs_p[s], cursor_p[s], dinv_p[s], n);
        cudaEventRecord(evScan, a);
        csr_fill_kernel<<<ebl, 256, 0, a>>>(row, col, cursor_p[s], csr_p[s], E);

        // stream b: stats zeroing + layer-0 HMMA GEMM (row-scaled fp16; waits on scan)
        cudaMemsetAsync(stats0_p[s], 0, 128 * sizeof(float), b);
        cudaMemsetAsync(stats1_p[s], 0, 256 * sizeof(float), b);
        cudaStreamWaitEvent(b, evScan, 0);
        hgemm_kernel<64, 0, 0><<<hbl, 256, 0, b>>>(x, nullptr, nullptr, w0[s],
                                                   dinv_p[s], m_p[s], n);
        cudaEventRecord(g_ev[5 + 5 * s], b);  // gemm0 done

        // join: gather layer 0 (fused BN stats), finalize BN0
        cudaStreamWaitEvent(a, g_ev[5 + 5 * s], 0);
        gather_kernel<64><<<wbl, 256, 0, a>>>(csr_p[s], offs_p[s], dinv_p[s], m_p[s],
                                              agg0_p[s], stats0_p[s], n);
        finalize_kernel<<<1, 64, 0, a>>>(stats0_p[s], bn_g0, bn_b0, ab0_p[s], n, 64);
        cudaEventRecord(evFin0, a);

        // layer 1: m = dinv*(h1' @ W1) fp16 on a; proj = h1' @ res1 fp32 on b
        hgemm_kernel<128, 1, 0><<<hbl, 256, 0, a>>>(agg0_p[s], x, ab0_p[s], w1[s],
                                                    dinv_p[s], m_p[s], n);
        cudaStreamWaitEvent(b, evFin0, 0);
        hgemm_kernel<128, 1, 1><<<hbl, 256, 0, b>>>(agg0_p[s], x, ab0_p[s], res1[s],
                                                    nullptr, proj_p[s], n);
        cudaEventRecord(evProj, b);

        gather_kernel<128><<<wbl, 256, 0, a>>>(csr_p[s], offs_p[s], dinv_p[s], m_p[s],
                                               agg1_p[s], stats1_p[s], n);
        finalize_kernel<<<1, 128, 0, a>>>(stats1_p[s], bn_g1, bn_b1, ab1_p[s], n, 128);
        cudaStreamWaitEvent(a, evProj, 0);
        cudaEventRecord(evDone, a);
    }

    // join both slices back to origin stream; head
    cudaStreamWaitEvent(0, g_ev[4], 0);
    cudaStreamWaitEvent(0, g_ev[9], 0);
    hfc1_kernel<<<hbl, 256>>>(agg1_p[0], proj_p[0], ab1_p[0],
                              agg1_p[1], proj_p[1], ab1_p[1],
                              fc1_w, fc1_b, hfc_p, n);
    fc2_softmax_kernel<<<wbl, 256>>>(hfc_p, fc2_w, fc2_b, (float*)d_out, n);
}